// round 7
// baseline (speedup 1.0000x reference)
#include <cuda_runtime.h>
#include <math.h>

#define BB 2048
#define DD 1024
#define RR 64
#define HH 256

// output layout: [out (B*1024)] [W1n (B*64*256)] [W2n (B*256*64)] [ssl_loss (B)]
#define OFF_OUT  0ull
#define OFF_W1   (2048ull*1024ull)
#define OFF_W2   (OFF_W1 + 2048ull*16384ull)
#define OFF_LOSS (OFF_W2 + 2048ull*16384ull)

__device__ float g_K[BB*RR];
__device__ float g_V[BB*RR];
__device__ float g_Q[BB*RR];
__device__ float g_eta[BB];

static __device__ __forceinline__ float wredsum(float v) {
#pragma unroll
    for (int o = 16; o; o >>= 1) v += __shfl_xor_sync(0xffffffffu, v, o);
    return v;
}

static __device__ __forceinline__ void gelu_fd(float x, float* y, float* dy) {
    const float c = 0.7978845608028654f;
    const float a = 0.044715f;
    float x2 = x * x;
    float u = c * (x + a * x * x2);
    float t = tanhf(u);
    float half1pt = 0.5f * (1.f + t);
    *y  = x * half1pt;
    *dy = half1pt + 0.5f * x * (1.f - t * t) * c * (1.f + 3.f * a * x2);
}

// ---------------------------------------------------------------------------
// proj + eta: blockIdx.y 0..2 -> k/v/q GEMMs; blockIdx.y==3 -> eta rows
// ---------------------------------------------------------------------------
__global__ void __launch_bounds__(256) proj_eta_kernel(
    const float* __restrict__ x,
    const float* __restrict__ Wk, const float* __restrict__ bk,
    const float* __restrict__ Wv, const float* __restrict__ bv,
    const float* __restrict__ Wq, const float* __restrict__ bq,
    const float* __restrict__ lr_w, const float* __restrict__ lr_b)
{
    const int tid = threadIdx.x;
    const int lane = tid & 31;
    const int wrp = tid >> 5;

    if (blockIdx.y == 3) {
        int rbase = blockIdx.x * 32 + wrp * 4;
#pragma unroll
        for (int jj = 0; jj < 4; jj++) {
            int row = rbase + jj;
            const float* xr = x + (size_t)row * DD;
            float s = 0.f;
#pragma unroll 8
            for (int j = lane; j < DD; j += 32) s = fmaf(xr[j], lr_w[j], s);
            s = wredsum(s);
            if (lane == 0) g_eta[row] = 0.1f / (1.f + expf(-(s + lr_b[0])));
        }
        return;
    }

    const int mat = blockIdx.y;
    const float* W    = (mat == 0) ? Wk : (mat == 1) ? Wv : Wq;
    const float* bias = (mat == 0) ? bk : (mat == 1) ? bv : bq;
    float* Cout       = (mat == 0) ? g_K : (mat == 1) ? g_V : g_Q;

    const int ntile = blockIdx.x & 1;
    const int mtile = blockIdx.x >> 1;
    const int m0 = mtile * 64, n0 = ntile * 32;

    __shared__ float As[32][68];
    __shared__ float Bs[32][32];

    const int tx = tid & 15;
    const int ty = tid >> 4;

    float acc[4][2] = {};

    for (int kt = 0; kt < DD; kt += 32) {
#pragma unroll
        for (int l = 0; l < 2; l++) {
            int li  = tid + l * 256;
            int row = li >> 3;
            int c4  = li & 7;
            float4 a = *(const float4*)(x + (size_t)(m0 + row) * DD + kt + c4 * 4);
            As[c4 * 4 + 0][row] = a.x;
            As[c4 * 4 + 1][row] = a.y;
            As[c4 * 4 + 2][row] = a.z;
            As[c4 * 4 + 3][row] = a.w;
        }
        {
            int row = tid >> 3;
            int c4  = tid & 7;
            float4 bv4 = *(const float4*)(W + (size_t)(kt + row) * RR + n0 + c4 * 4);
            *(float4*)(&Bs[row][c4 * 4]) = bv4;
        }
        __syncthreads();
#pragma unroll
        for (int k = 0; k < 32; k++) {
            float a0 = As[k][ty * 4 + 0], a1 = As[k][ty * 4 + 1];
            float a2 = As[k][ty * 4 + 2], a3 = As[k][ty * 4 + 3];
            float b0 = Bs[k][tx * 2 + 0], b1 = Bs[k][tx * 2 + 1];
            acc[0][0] = fmaf(a0, b0, acc[0][0]); acc[0][1] = fmaf(a0, b1, acc[0][1]);
            acc[1][0] = fmaf(a1, b0, acc[1][0]); acc[1][1] = fmaf(a1, b1, acc[1][1]);
            acc[2][0] = fmaf(a2, b0, acc[2][0]); acc[2][1] = fmaf(a2, b1, acc[2][1]);
            acc[3][0] = fmaf(a3, b0, acc[3][0]); acc[3][1] = fmaf(a3, b1, acc[3][1]);
        }
        __syncthreads();
    }
#pragma unroll
    for (int i = 0; i < 4; i++) {
        int row = m0 + ty * 4 + i;
        int col = n0 + tx * 2;
        float2 o;
        o.x = acc[i][0] + bias[col];
        o.y = acc[i][1] + bias[col + 1];
        *(float2*)(Cout + (size_t)row * RR + col) = o;
    }
}

// ---------------------------------------------------------------------------
// MEGA kernel: 128 blocks x 256 threads, 16 samples/block, one wave.
// ---------------------------------------------------------------------------
#define CS 16
#define O_W1S   0
#define O_W2S   16384
#define O_KX    33024
#define O_VX    34048
#define O_QX    35072
#define O_EK    36096
#define O_LNG   37120
#define O_LNB   37184
#define O_HPRE  37248
#define O_HV    41344
#define O_DHP   45440
#define O_ORR   49536
#define O_DOR   50560
#define O_ZL    51584
#define O_RED   52608
#define O_SCE   52672
#define O_SCQ   52688
#define O_SCH   52704
#define MEGA_FLOATS 52720
#define MEGA_BYTES  (MEGA_FLOATS * 4)

__global__ void __launch_bounds__(256, 1) mega_kernel(
    const float* __restrict__ W1, const float* __restrict__ W2,
    const float* __restrict__ Wo, const float* __restrict__ bo,
    const float* __restrict__ ln_g, const float* __restrict__ ln_b,
    float* __restrict__ outp)
{
    extern __shared__ float sm[];
    float* W1s  = sm + O_W1S;    // [64][256]
    float* W2s  = sm + O_W2S;    // [256][65]
    float* KX   = sm + O_KX;     // [16][64]
    float* VX   = sm + O_VX;
    float* QX   = sm + O_QX;
    float* EK   = sm + O_EK;     // eta*k [16][64]
    float* LNG  = sm + O_LNG;
    float* LNB  = sm + O_LNB;
    float* HPRE = sm + O_HPRE;   // [16][256] (becomes H2)
    float* HV   = sm + O_HV;     // [16][256]
    float* DHP  = sm + O_DHP;    // [16][256]
    float* ORR  = sm + O_ORR;    // [16][64]
    float* DOR  = sm + O_DOR;    // [16][64]
    float* ZL   = sm + O_ZL;     // [16][64]
    float* RED  = sm + O_RED;    // [16][4]
    float* SC_ETA = sm + O_SCE;
    float* SC_QK  = sm + O_SCQ;
    float* SC_HH  = sm + O_SCH;

    const int tid  = threadIdx.x;
    const int b0   = blockIdx.x * CS;
    const int lane = tid & 31;
    const int wrp  = tid >> 5;

    // ================= P0: stage =================
#pragma unroll
    for (int l = 0; l < 16; l++) {
        int i = (tid + l * 256) * 4;
        *(float4*)(W1s + i) = __ldg((const float4*)(W1 + i));
    }
#pragma unroll
    for (int l = 0; l < 16; l++) {
        int i4 = tid + l * 256;
        int idx = i4 * 4;
        int ii = idx >> 6, rr2 = idx & 63;
        float4 w = __ldg((const float4*)(W2 + idx));
        float* dst = W2s + ii * 65 + rr2;
        dst[0] = w.x; dst[1] = w.y; dst[2] = w.z; dst[3] = w.w;
    }
    *(float4*)(KX + tid * 4) = *(const float4*)(g_K + (size_t)b0 * 64 + tid * 4);
    *(float4*)(VX + tid * 4) = *(const float4*)(g_V + (size_t)b0 * 64 + tid * 4);
    *(float4*)(QX + tid * 4) = *(const float4*)(g_Q + (size_t)b0 * 64 + tid * 4);
    if (tid < 64) { LNG[tid] = ln_g[tid]; LNB[tid] = ln_b[tid]; }
    if (tid < CS) SC_ETA[tid] = g_eta[b0 + tid];
    __syncthreads();

    // EK = eta*k
#pragma unroll
    for (int l = 0; l < 4; l++) {
        int t = tid + l * 256;
        EK[t] = SC_ETA[t >> 6] * KX[t];
    }

    // ================= P1: hpre = k@W1, hv = gelu =================
    {
        const int c2 = tid & 127;
        const int sg = (tid >> 7) * 8;
        const float2* W1s2 = (const float2*)W1s;
        float acc0[8] = {}, acc1[8] = {};
#pragma unroll 4
        for (int r = 0; r < 64; r++) {
            float2 w = W1s2[r * 128 + c2];
#pragma unroll
            for (int j = 0; j < 8; j++) {
                float kv = KX[(sg + j) * 64 + r];
                acc0[j] = fmaf(w.x, kv, acc0[j]);
                acc1[j] = fmaf(w.y, kv, acc1[j]);
            }
        }
#pragma unroll
        for (int j = 0; j < 8; j++) {
            int s = sg + j;
            float y, dy;
            gelu_fd(acc0[j], &y, &dy);
            HPRE[s * 256 + 2 * c2] = acc0[j];
            HV[s * 256 + 2 * c2] = y;
            gelu_fd(acc1[j], &y, &dy);
            HPRE[s * 256 + 2 * c2 + 1] = acc1[j];
            HV[s * 256 + 2 * c2 + 1] = y;
        }
    }
    __syncthreads();

    // ================= P2: o = h@W2 =================
    {
        const int r = tid & 63, sq = tid >> 6;
        float acc[4] = {};
        for (int i = 0; i < 256; i++) {
            float w = W2s[i * 65 + r];
#pragma unroll
            for (int j = 0; j < 4; j++)
                acc[j] = fmaf(w, HV[(sq + 4 * j) * 256 + i], acc[j]);
        }
#pragma unroll
        for (int j = 0; j < 4; j++) ORR[(sq + 4 * j) * 64 + r] = acc[j];
    }
    __syncthreads();

    // ================= P3: LN fwd + loss + LN bwd + qk =================
#pragma unroll
    for (int sl = 0; sl < 2; sl++) {
        int s = wrp * 2 + sl;
        float o0 = ORR[s * 64 + lane], o1 = ORR[s * 64 + lane + 32];
        float mu = wredsum(o0 + o1) * (1.f / 64.f);
        float d0 = o0 - mu, d1 = o1 - mu;
        float var = wredsum(d0 * d0 + d1 * d1) * (1.f / 64.f);
        float sf = rsqrtf(var + 1e-6f);
        float n0 = d0 * sf, n1 = d1 * sf;
        float g0 = LNG[lane], g1 = LNG[lane + 32];
        float k0 = KX[s * 64 + lane], k1 = KX[s * 64 + lane + 32];
        float pred0 = k0 + n0 * g0 + LNB[lane];
        float pred1 = k1 + n1 * g1 + LNB[lane + 32];
        float e0 = pred0 - VX[s * 64 + lane], e1 = pred1 - VX[s * 64 + lane + 32];
        float loss = wredsum(e0 * e0 + e1 * e1) * (1.f / 64.f);
        float dn0 = e0 * (2.f / 64.f) * g0;
        float dn1 = e1 * (2.f / 64.f) * g1;
        float m1 = wredsum(dn0 + dn1) * (1.f / 64.f);
        float m2 = wredsum(dn0 * n0 + dn1 * n1) * (1.f / 64.f);
        DOR[s * 64 + lane]      = sf * (dn0 - m1 - n0 * m2);
        DOR[s * 64 + lane + 32] = sf * (dn1 - m1 - n1 * m2);
        float qk = wredsum(QX[s * 64 + lane] * k0 + QX[s * 64 + lane + 32] * k1);
        if (lane == 0) {
            SC_QK[s] = qk;
            outp[OFF_LOSS + b0 + s] = loss;
        }
    }
    __syncthreads();

    // ================= W2n STORE (early; drain overlaps all later phases) ===
    // W2n[s][i][r] = W2[i][r] - (eta*hv[s][i]) * dor[s][r]
    // per sample: 16384 floats = 4096 float4 chunks; total 65536 chunks
#pragma unroll 4
    for (int l = 0; l < 256; l++) {
        int idx = tid + l * 256;
        int s = idx >> 12;
        int rem = idx & 4095;          // chunk: i = rem>>4, r4 = rem&15
        int i = rem >> 4;
        float4 w = __ldg((const float4*)W2 + rem);
        float sc = SC_ETA[s] * HV[s * 256 + i];
        float4 d = *(float4*)(DOR + s * 64 + (rem & 15) * 4);
        float4 ov;
        ov.x = w.x - sc * d.x;
        ov.y = w.y - sc * d.y;
        ov.z = w.z - sc * d.z;
        ov.w = w.w - sc * d.w;
        *(float4*)(outp + OFF_W2 + (size_t)(b0 + s) * 16384 + rem * 4) = ov;
    }

    // ================= P4: dhp, h2, prod =================
    {
        const int i2 = tid & 127;
        const int sg = (tid >> 7) * 8;
        float acc0[8] = {}, acc1[8] = {};
#pragma unroll 4
        for (int r = 0; r < 64; r++) {
            float w0 = W2s[(2 * i2) * 65 + r];
            float w1 = W2s[(2 * i2 + 1) * 65 + r];
#pragma unroll
            for (int j = 0; j < 8; j++) {
                float dv = DOR[(sg + j) * 64 + r];
                acc0[j] = fmaf(w0, dv, acc0[j]);
                acc1[j] = fmaf(w1, dv, acc1[j]);
            }
        }
#pragma unroll
        for (int j = 0; j < 8; j++) {
            int s = sg + j;
            float y, dy;
            gelu_fd(HPRE[s * 256 + 2 * i2], &y, &dy);
            DHP[s * 256 + 2 * i2] = acc0[j] * dy;
            gelu_fd(HPRE[s * 256 + 2 * i2 + 1], &y, &dy);
            DHP[s * 256 + 2 * i2 + 1] = acc1[j] * dy;
        }
        const float2* W1s2 = (const float2*)W1s;
        float ac20[8] = {}, ac21[8] = {};
#pragma unroll 4
        for (int r = 0; r < 64; r++) {
            float2 w = W1s2[r * 128 + i2];
#pragma unroll
            for (int j = 0; j < 8; j++) {
                float qv = QX[(sg + j) * 64 + r];
                ac20[j] = fmaf(w.x, qv, ac20[j]);
                ac21[j] = fmaf(w.y, qv, ac21[j]);
            }
        }
        float prod[8];
#pragma unroll
        for (int j = 0; j < 8; j++) {
            int s = sg + j;
            float eqk = SC_ETA[s] * SC_QK[s];
            float d0 = DHP[s * 256 + 2 * i2];
            float d1 = DHP[s * 256 + 2 * i2 + 1];
            float y0, y1, dyt;
            gelu_fd(ac20[j] - eqk * d0, &y0, &dyt);
            gelu_fd(ac21[j] - eqk * d1, &y1, &dyt);
            HPRE[s * 256 + 2 * i2]     = y0;
            HPRE[s * 256 + 2 * i2 + 1] = y1;
            prod[j] = y0 * HV[s * 256 + 2 * i2] + y1 * HV[s * 256 + 2 * i2 + 1];
        }
#pragma unroll
        for (int j = 0; j < 8; j++) {
            float p = wredsum(prod[j]);
            if (lane == 0) RED[(sg + j) * 4 + (wrp & 3)] = p;
        }
    }
    __syncthreads();
    if (tid < CS)
        SC_HH[tid] = RED[tid * 4] + RED[tid * 4 + 1] + RED[tid * 4 + 2] + RED[tid * 4 + 3];
    __syncthreads();

    // ================= W1n STORE =================
    // W1n[s][r][i] = W1[r][i] - (eta*k[s][r]) * dhp[s][i]
#pragma unroll 4
    for (int l = 0; l < 256; l++) {
        int idx = tid + l * 256;
        int s = idx >> 12;
        int rem = idx & 4095;          // chunk: r = rem>>6, i4 = rem&63
        float4 w = __ldg((const float4*)W1 + rem);
        float sc = EK[s * 64 + (rem >> 6)];
        float4 d = *(float4*)(DHP + s * 256 + (rem & 63) * 4);
        float4 ov;
        ov.x = w.x - sc * d.x;
        ov.y = w.y - sc * d.y;
        ov.z = w.z - sc * d.z;
        ov.w = w.w - sc * d.w;
        *(float4*)(outp + OFF_W1 + (size_t)(b0 + s) * 16384 + rem * 4) = ov;
    }

    // ================= P5: o2 = h2@W2 - eta*hh*do =================
    {
        const int r = tid & 63, sq = tid >> 6;
        float acc[4] = {};
        for (int i = 0; i < 256; i++) {
            float w = W2s[i * 65 + r];
#pragma unroll
            for (int j = 0; j < 4; j++)
                acc[j] = fmaf(w, HPRE[(sq + 4 * j) * 256 + i], acc[j]);
        }
#pragma unroll
        for (int j = 0; j < 4; j++) {
            int s = sq + 4 * j;
            ORR[s * 64 + r] = acc[j] - SC_ETA[s] * SC_HH[s] * DOR[s * 64 + r];
        }
    }
    __syncthreads();

    // ================= P6: z = q + LN(o2) =================
#pragma unroll
    for (int sl = 0; sl < 2; sl++) {
        int s = wrp * 2 + sl;
        float o0 = ORR[s * 64 + lane], o1 = ORR[s * 64 + lane + 32];
        float mu = wredsum(o0 + o1) * (1.f / 64.f);
        float d0 = o0 - mu, d1 = o1 - mu;
        float var = wredsum(d0 * d0 + d1 * d1) * (1.f / 64.f);
        float sf = rsqrtf(var + 1e-6f);
        ZL[s * 64 + lane]      = QX[s * 64 + lane]      + (d0 * sf) * LNG[lane]      + LNB[lane];
        ZL[s * 64 + lane + 32] = QX[s * 64 + lane + 32] + (d1 * sf) * LNG[lane + 32] + LNB[lane + 32];
    }
    __syncthreads();

    // ================= P7: out = z @ Wo + bo (16 rows x 1024 cols) =========
    {
        const int sg4 = (tid >> 6) * 4;
        const int nb = (tid & 63) * 4;
#pragma unroll
        for (int nc = 0; nc < 4; nc++) {
            const int n0 = nb + nc * 256;
            float a0[4] = {}, a1[4] = {}, a2[4] = {}, a3[4] = {};
#pragma unroll 4
            for (int r = 0; r < 64; r++) {
                float4 w = __ldg((const float4*)(Wo + (size_t)r * 1024 + n0));
                float z0 = ZL[(sg4 + 0) * 64 + r];
                float z1 = ZL[(sg4 + 1) * 64 + r];
                float z2 = ZL[(sg4 + 2) * 64 + r];
                float z3 = ZL[(sg4 + 3) * 64 + r];
                a0[0] = fmaf(z0, w.x, a0[0]); a0[1] = fmaf(z0, w.y, a0[1]);
                a0[2] = fmaf(z0, w.z, a0[2]); a0[3] = fmaf(z0, w.w, a0[3]);
                a1[0] = fmaf(z1, w.x, a1[0]); a1[1] = fmaf(z1, w.y, a1[1]);
                a1[2] = fmaf(z1, w.z, a1[2]); a1[3] = fmaf(z1, w.w, a1[3]);
                a2[0] = fmaf(z2, w.x, a2[0]); a2[1] = fmaf(z2, w.y, a2[1]);
                a2[2] = fmaf(z2, w.z, a2[2]); a2[3] = fmaf(z2, w.w, a2[3]);
                a3[0] = fmaf(z3, w.x, a3[0]); a3[1] = fmaf(z3, w.y, a3[1]);
                a3[2] = fmaf(z3, w.z, a3[2]); a3[3] = fmaf(z3, w.w, a3[3]);
            }
            float4 bb = __ldg((const float4*)(bo + n0));
            float4 ov;
            ov.x = a0[0] + bb.x; ov.y = a0[1] + bb.y; ov.z = a0[2] + bb.z; ov.w = a0[3] + bb.w;
            *(float4*)(outp + OFF_OUT + (size_t)(b0 + sg4 + 0) * 1024 + n0) = ov;
            ov.x = a1[0] + bb.x; ov.y = a1[1] + bb.y; ov.z = a1[2] + bb.z; ov.w = a1[3] + bb.w;
            *(float4*)(outp + OFF_OUT + (size_t)(b0 + sg4 + 1) * 1024 + n0) = ov;
            ov.x = a2[0] + bb.x; ov.y = a2[1] + bb.y; ov.z = a2[2] + bb.z; ov.w = a2[3] + bb.w;
            *(float4*)(outp + OFF_OUT + (size_t)(b0 + sg4 + 2) * 1024 + n0) = ov;
            ov.x = a3[0] + bb.x; ov.y = a3[1] + bb.y; ov.z = a3[2] + bb.z; ov.w = a3[3] + bb.w;
            *(float4*)(outp + OFF_OUT + (size_t)(b0 + sg4 + 3) * 1024 + n0) = ov;
        }
    }
}

// ---------------------------------------------------------------------------
extern "C" void kernel_launch(void* const* d_in, const int* in_sizes, int n_in,
                              void* d_out, int out_size)
{
    const float* x    = (const float*)d_in[0];
    const float* Wk   = (const float*)d_in[1];
    const float* bk   = (const float*)d_in[2];
    const float* Wv   = (const float*)d_in[3];
    const float* bv   = (const float*)d_in[4];
    const float* Wq   = (const float*)d_in[5];
    const float* bq   = (const float*)d_in[6];
    const float* Wo   = (const float*)d_in[7];
    const float* bo   = (const float*)d_in[8];
    const float* ln_g = (const float*)d_in[9];
    const float* ln_b = (const float*)d_in[10];
    const float* lr_w = (const float*)d_in[11];
    const float* lr_b = (const float*)d_in[12];
    const float* W1   = (const float*)d_in[13];
    const float* W2   = (const float*)d_in[14];
    float* outp = (float*)d_out;

    cudaFuncSetAttribute(mega_kernel,
                         cudaFuncAttributeMaxDynamicSharedMemorySize, MEGA_BYTES);

    proj_eta_kernel<<<dim3(64, 4), 256>>>(x, Wk, bk, Wv, bv, Wq, bq, lr_w, lr_b);
    mega_kernel<<<128, 256, MEGA_BYTES>>>(W1, W2, Wo, bo, ln_g, ln_b, outp);
}

// round 8
// speedup vs baseline: 1.2132x; 1.2132x over previous
#include <cuda_runtime.h>
#include <math.h>

#define BB 2048
#define DD 1024
#define RR 64
#define HH 256

// output layout: [out (B*1024)] [W1n (B*64*256)] [W2n (B*256*64)] [ssl_loss (B)]
#define OFF_OUT  0ull
#define OFF_W1   (2048ull*1024ull)
#define OFF_W2   (OFF_W1 + 2048ull*16384ull)
#define OFF_LOSS (OFF_W2 + 2048ull*16384ull)

__device__ float g_K [BB*RR];
__device__ float g_V [BB*RR];
__device__ float g_Q [BB*RR];
__device__ float g_K2[BB*RR];
__device__ float g_V2[BB*RR];
__device__ float g_Q2[BB*RR];
__device__ float g_eta[BB];

static __device__ __forceinline__ float wredsum(float v) {
#pragma unroll
    for (int o = 16; o; o >>= 1) v += __shfl_xor_sync(0xffffffffu, v, o);
    return v;
}

static __device__ __forceinline__ void gelu_fd(float x, float* y, float* dy) {
    const float c = 0.7978845608028654f;
    const float a = 0.044715f;
    float x2 = x * x;
    float u = c * (x + a * x * x2);
    float t = tanhf(u);
    float half1pt = 0.5f * (1.f + t);
    *y  = x * half1pt;
    *dy = half1pt + 0.5f * x * (1.f - t * t) * c * (1.f + 3.f * a * x2);
}

// ---------------------------------------------------------------------------
// proj + eta.  grid (32, 7):
//   blockIdx.y in [0,6): mat = y>>1, ksplit = y&1  -> 64x64 tile, K half
//   blockIdx.y == 6: eta (32 blocks x 8 warps x 8 rows)
// micro 4x4: 16 FMA per 32 smem bytes -> FMA-balanced
// ---------------------------------------------------------------------------
__global__ void __launch_bounds__(256) proj_eta_kernel(
    const float* __restrict__ x,
    const float* __restrict__ Wk, const float* __restrict__ bk,
    const float* __restrict__ Wv, const float* __restrict__ bv,
    const float* __restrict__ Wq, const float* __restrict__ bq,
    const float* __restrict__ lr_w, const float* __restrict__ lr_b)
{
    const int tid = threadIdx.x;
    const int lane = tid & 31;
    const int wrp = tid >> 5;

    if (blockIdx.y == 6) {
        int rbase = blockIdx.x * 64 + wrp * 8;
#pragma unroll
        for (int jj = 0; jj < 8; jj++) {
            int row = rbase + jj;
            const float* xr = x + (size_t)row * DD;
            float s = 0.f;
#pragma unroll 8
            for (int j = lane; j < DD; j += 32) s = fmaf(xr[j], lr_w[j], s);
            s = wredsum(s);
            if (lane == 0) g_eta[row] = 0.1f / (1.f + expf(-(s + lr_b[0])));
        }
        return;
    }

    const int mat = blockIdx.y >> 1;
    const int ksp = blockIdx.y & 1;
    const float* W    = (mat == 0) ? Wk : (mat == 1) ? Wv : Wq;
    const float* bias = (mat == 0) ? bk : (mat == 1) ? bv : bq;
    float* Cout = (ksp == 0) ? ((mat == 0) ? g_K : (mat == 1) ? g_V : g_Q)
                             : ((mat == 0) ? g_K2 : (mat == 1) ? g_V2 : g_Q2);

    const int m0 = blockIdx.x * 64;
    const int k0 = ksp * 512;

    __shared__ float As[32][68];   // [k][m]
    __shared__ float Bs[32][64];   // [k][n]

    const int tx = tid & 15;       // n = tx*4
    const int ty = tid >> 4;       // m = ty*4

    float acc[4][4] = {};

    for (int kt = k0; kt < k0 + 512; kt += 32) {
#pragma unroll
        for (int l = 0; l < 2; l++) {
            int li  = tid + l * 256;
            int row = li >> 3;
            int c4  = li & 7;
            float4 a = *(const float4*)(x + (size_t)(m0 + row) * DD + kt + c4 * 4);
            As[c4 * 4 + 0][row] = a.x;
            As[c4 * 4 + 1][row] = a.y;
            As[c4 * 4 + 2][row] = a.z;
            As[c4 * 4 + 3][row] = a.w;
        }
#pragma unroll
        for (int l = 0; l < 2; l++) {
            int li  = tid + l * 256;
            int row = li >> 4;
            int c4  = li & 15;
            *(float4*)(&Bs[row][c4 * 4]) =
                *(const float4*)(W + (size_t)(kt + row) * RR + c4 * 4);
        }
        __syncthreads();
#pragma unroll
        for (int k = 0; k < 32; k++) {
            float4 a = *(const float4*)(&As[k][ty * 4]);
            float4 b = *(const float4*)(&Bs[k][tx * 4]);
            acc[0][0] = fmaf(a.x, b.x, acc[0][0]); acc[0][1] = fmaf(a.x, b.y, acc[0][1]);
            acc[0][2] = fmaf(a.x, b.z, acc[0][2]); acc[0][3] = fmaf(a.x, b.w, acc[0][3]);
            acc[1][0] = fmaf(a.y, b.x, acc[1][0]); acc[1][1] = fmaf(a.y, b.y, acc[1][1]);
            acc[1][2] = fmaf(a.y, b.z, acc[1][2]); acc[1][3] = fmaf(a.y, b.w, acc[1][3]);
            acc[2][0] = fmaf(a.z, b.x, acc[2][0]); acc[2][1] = fmaf(a.z, b.y, acc[2][1]);
            acc[2][2] = fmaf(a.z, b.z, acc[2][2]); acc[2][3] = fmaf(a.z, b.w, acc[2][3]);
            acc[3][0] = fmaf(a.w, b.x, acc[3][0]); acc[3][1] = fmaf(a.w, b.y, acc[3][1]);
            acc[3][2] = fmaf(a.w, b.z, acc[3][2]); acc[3][3] = fmaf(a.w, b.w, acc[3][3]);
        }
        __syncthreads();
    }
#pragma unroll
    for (int i = 0; i < 4; i++) {
        int row = m0 + ty * 4 + i;
        int col = tx * 4;
        float4 o;
        if (ksp == 0) {
            o.x = acc[i][0] + bias[col];
            o.y = acc[i][1] + bias[col + 1];
            o.z = acc[i][2] + bias[col + 2];
            o.w = acc[i][3] + bias[col + 3];
        } else {
            o.x = acc[i][0]; o.y = acc[i][1]; o.z = acc[i][2]; o.w = acc[i][3];
        }
        *(float4*)(Cout + (size_t)row * RR + col) = o;
    }
}

// ---------------------------------------------------------------------------
// MEGA kernel: 128 blocks x 512 threads, 16 samples/block, one wave.
// ---------------------------------------------------------------------------
#define CS 16
#define O_W1S   0
#define O_W2S   16384
#define O_KX    33024
#define O_VX    34048
#define O_QX    35072
#define O_EK    36096
#define O_LNG   37120
#define O_LNB   37184
#define O_HPRE  37248
#define O_HV    41344
#define O_DHP   45440
#define O_ORR   49536
#define O_DOR   50560
#define O_ZL    51584
#define O_RED   52608
#define O_SCE   52736
#define O_SCQ   52752
#define O_SCH   52768
#define MEGA_FLOATS 52784
#define MEGA_BYTES  (MEGA_FLOATS * 4)

__global__ void __launch_bounds__(512, 1) mega_kernel(
    const float* __restrict__ W1, const float* __restrict__ W2,
    const float* __restrict__ Wo, const float* __restrict__ bo,
    const float* __restrict__ ln_g, const float* __restrict__ ln_b,
    float* __restrict__ outp)
{
    extern __shared__ float sm[];
    float* W1s  = sm + O_W1S;    // [64][256]
    float* W2s  = sm + O_W2S;    // [256][65]
    float* KX   = sm + O_KX;     // [16][64]
    float* VX   = sm + O_VX;
    float* QX   = sm + O_QX;
    float* EK   = sm + O_EK;     // eta*k
    float* LNG  = sm + O_LNG;
    float* LNB  = sm + O_LNB;
    float* HPRE = sm + O_HPRE;   // [16][256] (becomes H2)
    float* HV   = sm + O_HV;     // [16][256]
    float* DHP  = sm + O_DHP;    // [16][256]
    float* ORR  = sm + O_ORR;    // [16][64]
    float* DOR  = sm + O_DOR;    // [16][64]
    float* ZL   = sm + O_ZL;     // [16][64]
    float* RED  = sm + O_RED;    // [16][8]
    float* SC_ETA = sm + O_SCE;
    float* SC_QK  = sm + O_SCQ;
    float* SC_HH  = sm + O_SCH;

    const int tid  = threadIdx.x;
    const int b0   = blockIdx.x * CS;
    const int lane = tid & 31;
    const int wrp  = tid >> 5;   // 0..15

    // ================= P0: stage =================
#pragma unroll
    for (int l = 0; l < 8; l++) {
        int i = (tid + l * 512) * 4;
        *(float4*)(W1s + i) = __ldg((const float4*)(W1 + i));
    }
#pragma unroll
    for (int l = 0; l < 8; l++) {
        int i4 = tid + l * 512;
        int idx = i4 * 4;
        int ii = idx >> 6, rr2 = idx & 63;
        float4 w = __ldg((const float4*)(W2 + idx));
        float* dst = W2s + ii * 65 + rr2;
        dst[0] = w.x; dst[1] = w.y; dst[2] = w.z; dst[3] = w.w;
    }
    // K/V/Q = primary + K-split partial
    for (int t = tid; t < 768; t += 512) {
        int seg = t >> 8, off = t & 255;
        const float4* p0; const float4* p1; float* dst;
        if (seg == 0)      { p0 = (const float4*)(g_K + (size_t)b0 * 64); p1 = (const float4*)(g_K2 + (size_t)b0 * 64); dst = KX; }
        else if (seg == 1) { p0 = (const float4*)(g_V + (size_t)b0 * 64); p1 = (const float4*)(g_V2 + (size_t)b0 * 64); dst = VX; }
        else               { p0 = (const float4*)(g_Q + (size_t)b0 * 64); p1 = (const float4*)(g_Q2 + (size_t)b0 * 64); dst = QX; }
        float4 a = p0[off], b = p1[off];
        float4 o; o.x = a.x + b.x; o.y = a.y + b.y; o.z = a.z + b.z; o.w = a.w + b.w;
        *(float4*)(dst + off * 4) = o;
    }
    if (tid < 64) { LNG[tid] = ln_g[tid]; LNB[tid] = ln_b[tid]; }
    if (tid < CS) SC_ETA[tid] = g_eta[b0 + tid];
    __syncthreads();

    // EK = eta*k
#pragma unroll
    for (int l = 0; l < 2; l++) {
        int t = tid + l * 512;
        EK[t] = SC_ETA[t >> 6] * KX[t];
    }

    // ================= P1: hpre = k@W1, hv = gelu =================
    {
        const int c  = tid & 255;
        const int sg = (tid >> 8) * 8;
        float acc[8] = {};
#pragma unroll 4
        for (int r = 0; r < 64; r++) {
            float w = W1s[r * 256 + c];
#pragma unroll
            for (int j = 0; j < 8; j++)
                acc[j] = fmaf(w, KX[(sg + j) * 64 + r], acc[j]);
        }
#pragma unroll
        for (int j = 0; j < 8; j++) {
            int s = sg + j;
            float y, dy;
            gelu_fd(acc[j], &y, &dy);
            HPRE[s * 256 + c] = acc[j];
            HV[s * 256 + c]   = y;
        }
    }
    __syncthreads();

    // ================= P2: o = h@W2 =================
    {
        const int r = tid & 63, sq = tid >> 6;   // sq in [0,8)
        float acc[2] = {};
        for (int i = 0; i < 256; i++) {
            float w = W2s[i * 65 + r];
            acc[0] = fmaf(w, HV[sq * 256 + i], acc[0]);
            acc[1] = fmaf(w, HV[(sq + 8) * 256 + i], acc[1]);
        }
        ORR[sq * 64 + r]       = acc[0];
        ORR[(sq + 8) * 64 + r] = acc[1];
    }
    __syncthreads();

    // ================= P3: LN fwd + loss + LN bwd + qk (warp = sample) ====
    {
        int s = wrp;
        float o0 = ORR[s * 64 + lane], o1 = ORR[s * 64 + lane + 32];
        float mu = wredsum(o0 + o1) * (1.f / 64.f);
        float d0 = o0 - mu, d1 = o1 - mu;
        float var = wredsum(d0 * d0 + d1 * d1) * (1.f / 64.f);
        float sf = rsqrtf(var + 1e-6f);
        float n0 = d0 * sf, n1 = d1 * sf;
        float g0 = LNG[lane], g1 = LNG[lane + 32];
        float k0 = KX[s * 64 + lane], k1 = KX[s * 64 + lane + 32];
        float pred0 = k0 + n0 * g0 + LNB[lane];
        float pred1 = k1 + n1 * g1 + LNB[lane + 32];
        float e0 = pred0 - VX[s * 64 + lane], e1 = pred1 - VX[s * 64 + lane + 32];
        float loss = wredsum(e0 * e0 + e1 * e1) * (1.f / 64.f);
        float dn0 = e0 * (2.f / 64.f) * g0;
        float dn1 = e1 * (2.f / 64.f) * g1;
        float m1 = wredsum(dn0 + dn1) * (1.f / 64.f);
        float m2 = wredsum(dn0 * n0 + dn1 * n1) * (1.f / 64.f);
        DOR[s * 64 + lane]      = sf * (dn0 - m1 - n0 * m2);
        DOR[s * 64 + lane + 32] = sf * (dn1 - m1 - n1 * m2);
        float qk = wredsum(QX[s * 64 + lane] * k0 + QX[s * 64 + lane + 32] * k1);
        if (lane == 0) {
            SC_QK[s] = qk;
            outp[OFF_LOSS + b0 + s] = loss;
        }
    }
    __syncthreads();

    // ================= W2n STORE (early drain) =================
    // W2n[s][i][r] = W2[i][r] - (eta*hv[s][i]) * dor[s][r]
#pragma unroll 4
    for (int l = 0; l < 128; l++) {
        int idx = tid + l * 512;
        int s = idx >> 12;
        int rem = idx & 4095;          // i = rem>>4, r4 = rem&15
        int i = rem >> 4;
        float4 w = __ldg((const float4*)W2 + rem);
        float sc = SC_ETA[s] * HV[s * 256 + i];
        float4 d = *(float4*)(DOR + s * 64 + (rem & 15) * 4);
        float4 ov;
        ov.x = w.x - sc * d.x;
        ov.y = w.y - sc * d.y;
        ov.z = w.z - sc * d.z;
        ov.w = w.w - sc * d.w;
        *(float4*)(outp + OFF_W2 + (size_t)(b0 + s) * 16384 + rem * 4) = ov;
    }

    // ================= P4: dhp, h2, prod =================
    {
        const int c  = tid & 255;
        const int sg = (tid >> 8) * 8;
        float acc[8] = {};
#pragma unroll 4
        for (int r = 0; r < 64; r++) {
            float w = W2s[c * 65 + r];
#pragma unroll
            for (int j = 0; j < 8; j++)
                acc[j] = fmaf(w, DOR[(sg + j) * 64 + r], acc[j]);
        }
#pragma unroll
        for (int j = 0; j < 8; j++) {
            int s = sg + j;
            float y, dy;
            gelu_fd(HPRE[s * 256 + c], &y, &dy);
            DHP[s * 256 + c] = acc[j] * dy;
        }
        float ac2[8] = {};
#pragma unroll 4
        for (int r = 0; r < 64; r++) {
            float w = W1s[r * 256 + c];
#pragma unroll
            for (int j = 0; j < 8; j++)
                ac2[j] = fmaf(w, QX[(sg + j) * 64 + r], ac2[j]);
        }
        float prod[8];
#pragma unroll
        for (int j = 0; j < 8; j++) {
            int s = sg + j;
            float eqk = SC_ETA[s] * SC_QK[s];
            float y, dyt;
            gelu_fd(ac2[j] - eqk * DHP[s * 256 + c], &y, &dyt);
            HPRE[s * 256 + c] = y;           // H2 overwrites HPRE
            prod[j] = y * HV[s * 256 + c];
        }
#pragma unroll
        for (int j = 0; j < 8; j++) {
            float p = wredsum(prod[j]);
            if (lane == 0) RED[(sg + j) * 8 + (wrp & 7)] = p;
        }
    }
    __syncthreads();
    if (tid < CS) {
        float hh = 0.f;
#pragma unroll
        for (int w = 0; w < 8; w++) hh += RED[tid * 8 + w];
        SC_HH[tid] = hh;
    }
    __syncthreads();

    // ================= W1n STORE =================
    // W1n[s][r][i] = W1[r][i] - (eta*k[s][r]) * dhp[s][i]
#pragma unroll 4
    for (int l = 0; l < 128; l++) {
        int idx = tid + l * 512;
        int s = idx >> 12;
        int rem = idx & 4095;          // r = rem>>6, i4 = rem&63
        float4 w = __ldg((const float4*)W1 + rem);
        float sc = EK[s * 64 + (rem >> 6)];
        float4 d = *(float4*)(DHP + s * 256 + (rem & 63) * 4);
        float4 ov;
        ov.x = w.x - sc * d.x;
        ov.y = w.y - sc * d.y;
        ov.z = w.z - sc * d.z;
        ov.w = w.w - sc * d.w;
        *(float4*)(outp + OFF_W1 + (size_t)(b0 + s) * 16384 + rem * 4) = ov;
    }

    // ================= P5: o2 = h2@W2 - eta*hh*do =================
    {
        const int r = tid & 63, sq = tid >> 6;
        float acc[2] = {};
        for (int i = 0; i < 256; i++) {
            float w = W2s[i * 65 + r];
            acc[0] = fmaf(w, HPRE[sq * 256 + i], acc[0]);
            acc[1] = fmaf(w, HPRE[(sq + 8) * 256 + i], acc[1]);
        }
        ORR[sq * 64 + r]       = acc[0] - SC_ETA[sq]     * SC_HH[sq]     * DOR[sq * 64 + r];
        ORR[(sq + 8) * 64 + r] = acc[1] - SC_ETA[sq + 8] * SC_HH[sq + 8] * DOR[(sq + 8) * 64 + r];
    }
    __syncthreads();

    // ================= P6: z = q + LN(o2) (warp = sample) =================
    {
        int s = wrp;
        float o0 = ORR[s * 64 + lane], o1 = ORR[s * 64 + lane + 32];
        float mu = wredsum(o0 + o1) * (1.f / 64.f);
        float d0 = o0 - mu, d1 = o1 - mu;
        float var = wredsum(d0 * d0 + d1 * d1) * (1.f / 64.f);
        float sf = rsqrtf(var + 1e-6f);
        ZL[s * 64 + lane]      = QX[s * 64 + lane]      + (d0 * sf) * LNG[lane]      + LNB[lane];
        ZL[s * 64 + lane + 32] = QX[s * 64 + lane + 32] + (d1 * sf) * LNG[lane + 32] + LNB[lane + 32];
    }
    __syncthreads();

    // ================= P7: out = z @ Wo + bo =================
    {
        const int sg4 = (tid >> 7) * 4;        // 4 rows per 128-thread group
        const int cb  = (tid & 127) * 4;       // 512 cols per pass
#pragma unroll
        for (int nc = 0; nc < 2; nc++) {
            const int n0 = cb + nc * 512;
            float a0[4] = {}, a1[4] = {}, a2[4] = {}, a3[4] = {};
#pragma unroll 4
            for (int r = 0; r < 64; r++) {
                float4 w = __ldg((const float4*)(Wo + (size_t)r * 1024 + n0));
                float z0 = ZL[(sg4 + 0) * 64 + r];
                float z1 = ZL[(sg4 + 1) * 64 + r];
                float z2 = ZL[(sg4 + 2) * 64 + r];
                float z3 = ZL[(sg4 + 3) * 64 + r];
                a0[0] = fmaf(z0, w.x, a0[0]); a0[1] = fmaf(z0, w.y, a0[1]);
                a0[2] = fmaf(z0, w.z, a0[2]); a0[3] = fmaf(z0, w.w, a0[3]);
                a1[0] = fmaf(z1, w.x, a1[0]); a1[1] = fmaf(z1, w.y, a1[1]);
                a1[2] = fmaf(z1, w.z, a1[2]); a1[3] = fmaf(z1, w.w, a1[3]);
                a2[0] = fmaf(z2, w.x, a2[0]); a2[1] = fmaf(z2, w.y, a2[1]);
                a2[2] = fmaf(z2, w.z, a2[2]); a2[3] = fmaf(z2, w.w, a2[3]);
                a3[0] = fmaf(z3, w.x, a3[0]); a3[1] = fmaf(z3, w.y, a3[1]);
                a3[2] = fmaf(z3, w.z, a3[2]); a3[3] = fmaf(z3, w.w, a3[3]);
            }
            float4 bb = __ldg((const float4*)(bo + n0));
            float4 ov;
            ov.x = a0[0] + bb.x; ov.y = a0[1] + bb.y; ov.z = a0[2] + bb.z; ov.w = a0[3] + bb.w;
            *(float4*)(outp + OFF_OUT + (size_t)(b0 + sg4 + 0) * 1024 + n0) = ov;
            ov.x = a1[0] + bb.x; ov.y = a1[1] + bb.y; ov.z = a1[2] + bb.z; ov.w = a1[3] + bb.w;
            *(float4*)(outp + OFF_OUT + (size_t)(b0 + sg4 + 1) * 1024 + n0) = ov;
            ov.x = a2[0] + bb.x; ov.y = a2[1] + bb.y; ov.z = a2[2] + bb.z; ov.w = a2[3] + bb.w;
            *(float4*)(outp + OFF_OUT + (size_t)(b0 + sg4 + 2) * 1024 + n0) = ov;
            ov.x = a3[0] + bb.x; ov.y = a3[1] + bb.y; ov.z = a3[2] + bb.z; ov.w = a3[3] + bb.w;
            *(float4*)(outp + OFF_OUT + (size_t)(b0 + sg4 + 3) * 1024 + n0) = ov;
        }
    }
}

// ---------------------------------------------------------------------------
extern "C" void kernel_launch(void* const* d_in, const int* in_sizes, int n_in,
                              void* d_out, int out_size)
{
    const float* x    = (const float*)d_in[0];
    const float* Wk   = (const float*)d_in[1];
    const float* bk   = (const float*)d_in[2];
    const float* Wv   = (const float*)d_in[3];
    const float* bv   = (const float*)d_in[4];
    const float* Wq   = (const float*)d_in[5];
    const float* bq   = (const float*)d_in[6];
    const float* Wo   = (const float*)d_in[7];
    const float* bo   = (const float*)d_in[8];
    const float* ln_g = (const float*)d_in[9];
    const float* ln_b = (const float*)d_in[10];
    const float* lr_w = (const float*)d_in[11];
    const float* lr_b = (const float*)d_in[12];
    const float* W1   = (const float*)d_in[13];
    const float* W2   = (const float*)d_in[14];
    float* outp = (float*)d_out;

    cudaFuncSetAttribute(mega_kernel,
                         cudaFuncAttributeMaxDynamicSharedMemorySize, MEGA_BYTES);

    proj_eta_kernel<<<dim3(32, 7), 256>>>(x, Wk, bk, Wv, bv, Wq, bq, lr_w, lr_b);
    mega_kernel<<<128, 512, MEGA_BYTES>>>(W1, W2, Wo, bo, ln_g, ln_b, outp);
}

// round 9
// speedup vs baseline: 1.3278x; 1.0945x over previous
#include <cuda_runtime.h>
#include <math.h>

#define BB 2048
#define DD 1024
#define RR 64
#define HH 256

// output layout: [out (B*1024)] [W1n (B*64*256)] [W2n (B*256*64)] [ssl_loss (B)]
#define OFF_OUT  0ull
#define OFF_W1   (2048ull*1024ull)
#define OFF_W2   (OFF_W1 + 2048ull*16384ull)
#define OFF_LOSS (OFF_W2 + 2048ull*16384ull)

__device__ float g_K [BB*RR];
__device__ float g_V [BB*RR];
__device__ float g_Q [BB*RR];
__device__ float g_K2[BB*RR];
__device__ float g_V2[BB*RR];
__device__ float g_Q2[BB*RR];
__device__ float g_eta[BB];

static __device__ __forceinline__ float wredsum(float v) {
#pragma unroll
    for (int o = 16; o; o >>= 1) v += __shfl_xor_sync(0xffffffffu, v, o);
    return v;
}

static __device__ __forceinline__ void gelu_fd(float x, float* y, float* dy) {
    const float c = 0.7978845608028654f;
    const float a = 0.044715f;
    float x2 = x * x;
    float u = c * (x + a * x * x2);
    float t = tanhf(u);
    float half1pt = 0.5f * (1.f + t);
    *y  = x * half1pt;
    *dy = half1pt + 0.5f * x * (1.f - t * t) * c * (1.f + 3.f * a * x2);
}

// ---------------------------------------------------------------------------
// proj + eta.  grid (32, 7): y<6 -> mat=y>>1, ksplit=y&1; y==6 -> eta
// ---------------------------------------------------------------------------
__global__ void __launch_bounds__(256) proj_eta_kernel(
    const float* __restrict__ x,
    const float* __restrict__ Wk, const float* __restrict__ bk,
    const float* __restrict__ Wv, const float* __restrict__ bv,
    const float* __restrict__ Wq, const float* __restrict__ bq,
    const float* __restrict__ lr_w, const float* __restrict__ lr_b)
{
    const int tid = threadIdx.x;
    const int lane = tid & 31;
    const int wrp = tid >> 5;

    if (blockIdx.y == 6) {
        int rbase = blockIdx.x * 64 + wrp * 8;
#pragma unroll
        for (int jj = 0; jj < 8; jj++) {
            int row = rbase + jj;
            const float* xr = x + (size_t)row * DD;
            float s = 0.f;
#pragma unroll 8
            for (int j = lane; j < DD; j += 32) s = fmaf(xr[j], lr_w[j], s);
            s = wredsum(s);
            if (lane == 0) g_eta[row] = 0.1f / (1.f + expf(-(s + lr_b[0])));
        }
        return;
    }

    const int mat = blockIdx.y >> 1;
    const int ksp = blockIdx.y & 1;
    const float* W    = (mat == 0) ? Wk : (mat == 1) ? Wv : Wq;
    const float* bias = (mat == 0) ? bk : (mat == 1) ? bv : bq;
    float* Cout = (ksp == 0) ? ((mat == 0) ? g_K : (mat == 1) ? g_V : g_Q)
                             : ((mat == 0) ? g_K2 : (mat == 1) ? g_V2 : g_Q2);

    const int m0 = blockIdx.x * 64;
    const int k0 = ksp * 512;

    __shared__ float As[32][68];
    __shared__ float Bs[32][64];

    const int tx = tid & 15;
    const int ty = tid >> 4;

    float acc[4][4] = {};

    for (int kt = k0; kt < k0 + 512; kt += 32) {
#pragma unroll
        for (int l = 0; l < 2; l++) {
            int li  = tid + l * 256;
            int row = li >> 3;
            int c4  = li & 7;
            float4 a = *(const float4*)(x + (size_t)(m0 + row) * DD + kt + c4 * 4);
            As[c4 * 4 + 0][row] = a.x;
            As[c4 * 4 + 1][row] = a.y;
            As[c4 * 4 + 2][row] = a.z;
            As[c4 * 4 + 3][row] = a.w;
        }
#pragma unroll
        for (int l = 0; l < 2; l++) {
            int li  = tid + l * 256;
            int row = li >> 4;
            int c4  = li & 15;
            *(float4*)(&Bs[row][c4 * 4]) =
                *(const float4*)(W + (size_t)(kt + row) * RR + c4 * 4);
        }
        __syncthreads();
#pragma unroll
        for (int k = 0; k < 32; k++) {
            float4 a = *(const float4*)(&As[k][ty * 4]);
            float4 b = *(const float4*)(&Bs[k][tx * 4]);
            acc[0][0] = fmaf(a.x, b.x, acc[0][0]); acc[0][1] = fmaf(a.x, b.y, acc[0][1]);
            acc[0][2] = fmaf(a.x, b.z, acc[0][2]); acc[0][3] = fmaf(a.x, b.w, acc[0][3]);
            acc[1][0] = fmaf(a.y, b.x, acc[1][0]); acc[1][1] = fmaf(a.y, b.y, acc[1][1]);
            acc[1][2] = fmaf(a.y, b.z, acc[1][2]); acc[1][3] = fmaf(a.y, b.w, acc[1][3]);
            acc[2][0] = fmaf(a.z, b.x, acc[2][0]); acc[2][1] = fmaf(a.z, b.y, acc[2][1]);
            acc[2][2] = fmaf(a.z, b.z, acc[2][2]); acc[2][3] = fmaf(a.z, b.w, acc[2][3]);
            acc[3][0] = fmaf(a.w, b.x, acc[3][0]); acc[3][1] = fmaf(a.w, b.y, acc[3][1]);
            acc[3][2] = fmaf(a.w, b.z, acc[3][2]); acc[3][3] = fmaf(a.w, b.w, acc[3][3]);
        }
        __syncthreads();
    }
#pragma unroll
    for (int i = 0; i < 4; i++) {
        int row = m0 + ty * 4 + i;
        int col = tx * 4;
        float4 o;
        if (ksp == 0) {
            o.x = acc[i][0] + bias[col];
            o.y = acc[i][1] + bias[col + 1];
            o.z = acc[i][2] + bias[col + 2];
            o.w = acc[i][3] + bias[col + 3];
        } else {
            o.x = acc[i][0]; o.y = acc[i][1]; o.z = acc[i][2]; o.w = acc[i][3];
        }
        *(float4*)(Cout + (size_t)row * RR + col) = o;
    }
}

// ---------------------------------------------------------------------------
// MEGA kernel: 128 blocks x 1024 threads, 16 samples/block, one wave.
// ---------------------------------------------------------------------------
#define CS 16
#define O_W1S   0
#define O_W2S   16384
#define O_KX    33024
#define O_VX    34048
#define O_QX    35072
#define O_EK    36096
#define O_LNG   37120
#define O_LNB   37184
#define O_HPRE  37248
#define O_HV    41344
#define O_DHP   45440
#define O_ORR   49536
#define O_DOR   50560
#define O_ZL    51584
#define O_RED   52608
#define O_SCE   52736
#define O_SCQ   52752
#define O_SCH   52768
#define MEGA_FLOATS 52784
#define MEGA_BYTES  (MEGA_FLOATS * 4)

__global__ void __launch_bounds__(1024, 1) mega_kernel(
    const float* __restrict__ W1, const float* __restrict__ W2,
    const float* __restrict__ Wo, const float* __restrict__ bo,
    const float* __restrict__ ln_g, const float* __restrict__ ln_b,
    float* __restrict__ outp)
{
    extern __shared__ float sm[];
    float* W1s  = sm + O_W1S;    // [64][256]
    float* W2s  = sm + O_W2S;    // [256][65]
    float* KX   = sm + O_KX;     // [16][64]
    float* VX   = sm + O_VX;
    float* QX   = sm + O_QX;
    float* EK   = sm + O_EK;
    float* LNG  = sm + O_LNG;
    float* LNB  = sm + O_LNB;
    float* HPRE = sm + O_HPRE;   // [16][256] (becomes H2)
    float* HV   = sm + O_HV;     // [16][256]
    float* DHP  = sm + O_DHP;    // [16][256]
    float* ORR  = sm + O_ORR;    // [16][64]
    float* DOR  = sm + O_DOR;    // [16][64]
    float* ZL   = sm + O_ZL;     // [16][64]
    float* RED  = sm + O_RED;    // [16][8]
    float* SC_ETA = sm + O_SCE;
    float* SC_QK  = sm + O_SCQ;
    float* SC_HH  = sm + O_SCH;

    const int tid  = threadIdx.x;
    const int b0   = blockIdx.x * CS;
    const int lane = tid & 31;
    const int wrp  = tid >> 5;   // 0..31

    // ================= P0: stage =================
#pragma unroll
    for (int l = 0; l < 4; l++) {
        int i = (tid + l * 1024) * 4;
        *(float4*)(W1s + i) = __ldg((const float4*)(W1 + i));
    }
#pragma unroll
    for (int l = 0; l < 4; l++) {
        int i4 = tid + l * 1024;
        int idx = i4 * 4;
        int ii = idx >> 6, rr2 = idx & 63;
        float4 w = __ldg((const float4*)(W2 + idx));
        float* dst = W2s + ii * 65 + rr2;
        dst[0] = w.x; dst[1] = w.y; dst[2] = w.z; dst[3] = w.w;
    }
    if (tid < 768) {
        int seg = tid >> 8, off = tid & 255;
        const float4* p0; const float4* p1; float* dst;
        if (seg == 0)      { p0 = (const float4*)(g_K + (size_t)b0 * 64); p1 = (const float4*)(g_K2 + (size_t)b0 * 64); dst = KX; }
        else if (seg == 1) { p0 = (const float4*)(g_V + (size_t)b0 * 64); p1 = (const float4*)(g_V2 + (size_t)b0 * 64); dst = VX; }
        else               { p0 = (const float4*)(g_Q + (size_t)b0 * 64); p1 = (const float4*)(g_Q2 + (size_t)b0 * 64); dst = QX; }
        float4 a = p0[off], b = p1[off];
        float4 o; o.x = a.x + b.x; o.y = a.y + b.y; o.z = a.z + b.z; o.w = a.w + b.w;
        *(float4*)(dst + off * 4) = o;
    }
    if (tid < 64) { LNG[tid] = ln_g[tid]; LNB[tid] = ln_b[tid]; }
    if (tid >= 64 && tid < 64 + CS) SC_ETA[tid - 64] = g_eta[b0 + tid - 64];
    __syncthreads();

    // EK = eta*k
    EK[tid] = SC_ETA[tid >> 6] * KX[tid];

    // ================= P1: hpre = k@W1, hv = gelu =================
    {
        const int c  = tid & 255;
        const int sg = (tid >> 8) * 4;
        float acc[4] = {};
#pragma unroll 4
        for (int r = 0; r < 64; r++) {
            float w = W1s[r * 256 + c];
#pragma unroll
            for (int j = 0; j < 4; j++)
                acc[j] = fmaf(w, KX[(sg + j) * 64 + r], acc[j]);
        }
#pragma unroll
        for (int j = 0; j < 4; j++) {
            int s = sg + j;
            float y, dy;
            gelu_fd(acc[j], &y, &dy);
            HPRE[s * 256 + c] = acc[j];
            HV[s * 256 + c]   = y;
        }
    }
    __syncthreads();

    // ================= P2: o = h@W2 =================
    {
        const int r = tid & 63, sq = tid >> 6;   // sq in [0,16)
        float acc = 0.f;
#pragma unroll 8
        for (int i = 0; i < 256; i++)
            acc = fmaf(W2s[i * 65 + r], HV[sq * 256 + i], acc);
        ORR[sq * 64 + r] = acc;
    }
    __syncthreads();

    // ================= P3: LN fwd + loss + LN bwd + qk (warp=sample) ======
    if (wrp < CS) {
        int s = wrp;
        float o0 = ORR[s * 64 + lane], o1 = ORR[s * 64 + lane + 32];
        float mu = wredsum(o0 + o1) * (1.f / 64.f);
        float d0 = o0 - mu, d1 = o1 - mu;
        float var = wredsum(d0 * d0 + d1 * d1) * (1.f / 64.f);
        float sf = rsqrtf(var + 1e-6f);
        float n0 = d0 * sf, n1 = d1 * sf;
        float g0 = LNG[lane], g1 = LNG[lane + 32];
        float k0 = KX[s * 64 + lane], k1 = KX[s * 64 + lane + 32];
        float pred0 = k0 + n0 * g0 + LNB[lane];
        float pred1 = k1 + n1 * g1 + LNB[lane + 32];
        float e0 = pred0 - VX[s * 64 + lane], e1 = pred1 - VX[s * 64 + lane + 32];
        float loss = wredsum(e0 * e0 + e1 * e1) * (1.f / 64.f);
        float dn0 = e0 * (2.f / 64.f) * g0;
        float dn1 = e1 * (2.f / 64.f) * g1;
        float m1 = wredsum(dn0 + dn1) * (1.f / 64.f);
        float m2 = wredsum(dn0 * n0 + dn1 * n1) * (1.f / 64.f);
        DOR[s * 64 + lane]      = sf * (dn0 - m1 - n0 * m2);
        DOR[s * 64 + lane + 32] = sf * (dn1 - m1 - n1 * m2);
        float qk = wredsum(QX[s * 64 + lane] * k0 + QX[s * 64 + lane + 32] * k1);
        if (lane == 0) {
            SC_QK[s] = qk;
            outp[OFF_LOSS + b0 + s] = loss;
        }
    }
    __syncthreads();

    // ================= W2n STORE (warp-structured, early drain) ===========
    // warp w: s = w>>1, half = w&1; lane: r4 = lane&15, ihp = lane>>4
    // d (DOR float4) lives in registers for the whole loop.
    {
        const int s    = wrp >> 1;
        const int half = wrp & 1;
        const int r4   = lane & 15;
        const int ihp  = lane >> 4;
        const float eta_s = SC_ETA[s];
        const float4 d = *(const float4*)(DOR + s * 64 + r4 * 4);
        const float* hvrow = HV + s * 256;
        float* dst = outp + OFF_W2 + (size_t)(b0 + s) * 16384;
        int i = half * 128 + ihp;
#pragma unroll 4
        for (int ii = 0; ii < 64; ii++, i += 2) {
            int rem = i * 16 + r4;
            float4 w = __ldg((const float4*)W2 + rem);
            float sc = eta_s * hvrow[i];
            float4 ov;
            ov.x = w.x - sc * d.x;
            ov.y = w.y - sc * d.y;
            ov.z = w.z - sc * d.z;
            ov.w = w.w - sc * d.w;
            *(float4*)(dst + rem * 4) = ov;
        }
    }

    // ================= P4: dhp, h2, prod =================
    {
        const int c  = tid & 255;
        const int sg = (tid >> 8) * 4;
        float acc[4] = {};
#pragma unroll 4
        for (int r = 0; r < 64; r++) {
            float w = W2s[c * 65 + r];
#pragma unroll
            for (int j = 0; j < 4; j++)
                acc[j] = fmaf(w, DOR[(sg + j) * 64 + r], acc[j]);
        }
#pragma unroll
        for (int j = 0; j < 4; j++) {
            int s = sg + j;
            float y, dy;
            gelu_fd(HPRE[s * 256 + c], &y, &dy);
            DHP[s * 256 + c] = acc[j] * dy;
        }
        float ac2[4] = {};
#pragma unroll 4
        for (int r = 0; r < 64; r++) {
            float w = W1s[r * 256 + c];
#pragma unroll
            for (int j = 0; j < 4; j++)
                ac2[j] = fmaf(w, QX[(sg + j) * 64 + r], ac2[j]);
        }
        float prod[4];
#pragma unroll
        for (int j = 0; j < 4; j++) {
            int s = sg + j;
            float eqk = SC_ETA[s] * SC_QK[s];
            float y, dyt;
            gelu_fd(ac2[j] - eqk * DHP[s * 256 + c], &y, &dyt);
            HPRE[s * 256 + c] = y;
            prod[j] = y * HV[s * 256 + c];
        }
#pragma unroll
        for (int j = 0; j < 4; j++) {
            float p = wredsum(prod[j]);
            if (lane == 0) RED[(sg + j) * 8 + (wrp & 7)] = p;
        }
    }
    __syncthreads();
    if (tid < CS) {
        float hh = 0.f;
#pragma unroll
        for (int w = 0; w < 8; w++) hh += RED[tid * 8 + w];
        SC_HH[tid] = hh;
    }
    __syncthreads();

    // ================= W1n STORE (warp-structured) =================
    // warp w: s = w>>1, half = w&1; lane covers i4 = lane and lane+32.
    // DHP float4s live in registers for the whole loop.
    {
        const int s    = wrp >> 1;
        const int half = wrp & 1;
        const float4 d0 = *(const float4*)(DHP + s * 256 + lane * 4);
        const float4 d1 = *(const float4*)(DHP + s * 256 + (lane + 32) * 4);
        const float* ekrow = EK + s * 64;
        float* dst = outp + OFF_W1 + (size_t)(b0 + s) * 16384;
#pragma unroll 4
        for (int rr = 0; rr < 32; rr++) {
            int r = half * 32 + rr;
            float sc = ekrow[r];
            int rem0 = r * 64 + lane;
            int rem1 = rem0 + 32;
            float4 w0 = __ldg((const float4*)W1 + rem0);
            float4 w1 = __ldg((const float4*)W1 + rem1);
            float4 ov;
            ov.x = w0.x - sc * d0.x;
            ov.y = w0.y - sc * d0.y;
            ov.z = w0.z - sc * d0.z;
            ov.w = w0.w - sc * d0.w;
            *(float4*)(dst + rem0 * 4) = ov;
            ov.x = w1.x - sc * d1.x;
            ov.y = w1.y - sc * d1.y;
            ov.z = w1.z - sc * d1.z;
            ov.w = w1.w - sc * d1.w;
            *(float4*)(dst + rem1 * 4) = ov;
        }
    }

    // ================= P5: o2 = h2@W2 - eta*hh*do =================
    {
        const int r = tid & 63, sq = tid >> 6;
        float acc = 0.f;
#pragma unroll 8
        for (int i = 0; i < 256; i++)
            acc = fmaf(W2s[i * 65 + r], HPRE[sq * 256 + i], acc);
        ORR[sq * 64 + r] = acc - SC_ETA[sq] * SC_HH[sq] * DOR[sq * 64 + r];
    }
    __syncthreads();

    // ================= P6: z = q + LN(o2) (warp=sample) =================
    if (wrp < CS) {
        int s = wrp;
        float o0 = ORR[s * 64 + lane], o1 = ORR[s * 64 + lane + 32];
        float mu = wredsum(o0 + o1) * (1.f / 64.f);
        float d0 = o0 - mu, d1 = o1 - mu;
        float var = wredsum(d0 * d0 + d1 * d1) * (1.f / 64.f);
        float sf = rsqrtf(var + 1e-6f);
        ZL[s * 64 + lane]      = QX[s * 64 + lane]      + (d0 * sf) * LNG[lane]      + LNB[lane];
        ZL[s * 64 + lane + 32] = QX[s * 64 + lane + 32] + (d1 * sf) * LNG[lane + 32] + LNB[lane + 32];
    }
    __syncthreads();

    // ================= P7: out = z @ Wo + bo (one pass, 1024 cols) ========
    {
        const int sg4 = (tid >> 8) * 4;        // 4 rows per 256-thread group
        const int n0  = (tid & 255) * 4;       // all 1024 cols in one pass
        float a0[4] = {}, a1[4] = {}, a2[4] = {}, a3[4] = {};
#pragma unroll 4
        for (int r = 0; r < 64; r++) {
            float4 w = __ldg((const float4*)(Wo + (size_t)r * 1024 + n0));
            float z0 = ZL[(sg4 + 0) * 64 + r];
            float z1 = ZL[(sg4 + 1) * 64 + r];
            float z2 = ZL[(sg4 + 2) * 64 + r];
            float z3 = ZL[(sg4 + 3) * 64 + r];
            a0[0] = fmaf(z0, w.x, a0[0]); a0[1] = fmaf(z0, w.y, a0[1]);
            a0[2] = fmaf(z0, w.z, a0[2]); a0[3] = fmaf(z0, w.w, a0[3]);
            a1[0] = fmaf(z1, w.x, a1[0]); a1[1] = fmaf(z1, w.y, a1[1]);
            a1[2] = fmaf(z1, w.z, a1[2]); a1[3] = fmaf(z1, w.w, a1[3]);
            a2[0] = fmaf(z2, w.x, a2[0]); a2[1] = fmaf(z2, w.y, a2[1]);
            a2[2] = fmaf(z2, w.z, a2[2]); a2[3] = fmaf(z2, w.w, a2[3]);
            a3[0] = fmaf(z3, w.x, a3[0]); a3[1] = fmaf(z3, w.y, a3[1]);
            a3[2] = fmaf(z3, w.z, a3[2]); a3[3] = fmaf(z3, w.w, a3[3]);
        }
        float4 bb = __ldg((const float4*)(bo + n0));
        float4 ov;
        ov.x = a0[0] + bb.x; ov.y = a0[1] + bb.y; ov.z = a0[2] + bb.z; ov.w = a0[3] + bb.w;
        *(float4*)(outp + OFF_OUT + (size_t)(b0 + sg4 + 0) * 1024 + n0) = ov;
        ov.x = a1[0] + bb.x; ov.y = a1[1] + bb.y; ov.z = a1[2] + bb.z; ov.w = a1[3] + bb.w;
        *(float4*)(outp + OFF_OUT + (size_t)(b0 + sg4 + 1) * 1024 + n0) = ov;
        ov.x = a2[0] + bb.x; ov.y = a2[1] + bb.y; ov.z = a2[2] + bb.z; ov.w = a2[3] + bb.w;
        *(float4*)(outp + OFF_OUT + (size_t)(b0 + sg4 + 2) * 1024 + n0) = ov;
        ov.x = a3[0] + bb.x; ov.y = a3[1] + bb.y; ov.z = a3[2] + bb.z; ov.w = a3[3] + bb.w;
        *(float4*)(outp + OFF_OUT + (size_t)(b0 + sg4 + 3) * 1024 + n0) = ov;
    }
}

// ---------------------------------------------------------------------------
extern "C" void kernel_launch(void* const* d_in, const int* in_sizes, int n_in,
                              void* d_out, int out_size)
{
    const float* x    = (const float*)d_in[0];
    const float* Wk   = (const float*)d_in[1];
    const float* bk   = (const float*)d_in[2];
    const float* Wv   = (const float*)d_in[3];
    const float* bv   = (const float*)d_in[4];
    const float* Wq   = (const float*)d_in[5];
    const float* bq   = (const float*)d_in[6];
    const float* Wo   = (const float*)d_in[7];
    const float* bo   = (const float*)d_in[8];
    const float* ln_g = (const float*)d_in[9];
    const float* ln_b = (const float*)d_in[10];
    const float* lr_w = (const float*)d_in[11];
    const float* lr_b = (const float*)d_in[12];
    const float* W1   = (const float*)d_in[13];
    const float* W2   = (const float*)d_in[14];
    float* outp = (float*)d_out;

    cudaFuncSetAttribute(mega_kernel,
                         cudaFuncAttributeMaxDynamicSharedMemorySize, MEGA_BYTES);

    proj_eta_kernel<<<dim3(32, 7), 256>>>(x, Wk, bk, Wv, bv, Wq, bq, lr_w, lr_b);
    mega_kernel<<<128, 1024, MEGA_BYTES>>>(W1, W2, Wo, bo, ln_g, ln_b, outp);
}

// round 10
// speedup vs baseline: 1.4835x; 1.1173x over previous
#include <cuda_runtime.h>
#include <math.h>

#define BB 2048
#define DD 1024
#define RR 64
#define HH 256

// output layout: [out (B*1024)] [W1n (B*64*256)] [W2n (B*256*64)] [ssl_loss (B)]
#define OFF_OUT  0ull
#define OFF_W1   (2048ull*1024ull)
#define OFF_W2   (OFF_W1 + 2048ull*16384ull)
#define OFF_LOSS (OFF_W2 + 2048ull*16384ull)

__device__ float g_K [BB*RR];
__device__ float g_V [BB*RR];
__device__ float g_Q [BB*RR];
__device__ float g_K2[BB*RR];
__device__ float g_V2[BB*RR];
__device__ float g_Q2[BB*RR];
__device__ float g_eta[BB];

static __device__ __forceinline__ float wredsum(float v) {
#pragma unroll
    for (int o = 16; o; o >>= 1) v += __shfl_xor_sync(0xffffffffu, v, o);
    return v;
}

static __device__ __forceinline__ void gelu_fd(float x, float* y, float* dy) {
    const float c = 0.7978845608028654f;
    const float a = 0.044715f;
    float x2 = x * x;
    float u = c * (x + a * x * x2);
    float t = tanhf(u);
    float half1pt = 0.5f * (1.f + t);
    *y  = x * half1pt;
    *dy = half1pt + 0.5f * x * (1.f - t * t) * c * (1.f + 3.f * a * x2);
}

// ---------------------------------------------------------------------------
// proj + eta, flat grid of 448 x 128-thread blocks:
//   bid < 384: proj task; mat = bid/128, rem = bid%128, ksp = rem&1,
//              m0 = (rem>>1)*32  -> 32M x 64N tile, K half of 512
//   bid >= 384: eta block (32 rows each, 64 blocks)
// ---------------------------------------------------------------------------
__global__ void __launch_bounds__(128) proj_eta_kernel(
    const float* __restrict__ x,
    const float* __restrict__ Wk, const float* __restrict__ bk,
    const float* __restrict__ Wv, const float* __restrict__ bv,
    const float* __restrict__ Wq, const float* __restrict__ bq,
    const float* __restrict__ lr_w, const float* __restrict__ lr_b)
{
    const int tid = threadIdx.x;
    const int lane = tid & 31;
    const int wrp = tid >> 5;
    const int bid = blockIdx.x;

    if (bid >= 384) {
        int rbase = (bid - 384) * 32 + wrp * 8;
#pragma unroll
        for (int jj = 0; jj < 8; jj++) {
            int row = rbase + jj;
            const float* xr = x + (size_t)row * DD;
            float s = 0.f;
#pragma unroll 8
            for (int j = lane; j < DD; j += 32) s = fmaf(xr[j], lr_w[j], s);
            s = wredsum(s);
            if (lane == 0) g_eta[row] = 0.1f / (1.f + expf(-(s + lr_b[0])));
        }
        return;
    }

    const int mat = bid / 128;
    const int rem = bid % 128;
    const int ksp = rem & 1;
    const int m0  = (rem >> 1) * 32;
    const int k0  = ksp * 512;

    const float* W    = (mat == 0) ? Wk : (mat == 1) ? Wv : Wq;
    const float* bias = (mat == 0) ? bk : (mat == 1) ? bv : bq;
    float* Cout = (ksp == 0) ? ((mat == 0) ? g_K : (mat == 1) ? g_V : g_Q)
                             : ((mat == 0) ? g_K2 : (mat == 1) ? g_V2 : g_Q2);

    __shared__ float As[32][36];   // [k][m], 32 rows m, padded
    __shared__ float Bs[32][64];   // [k][n]

    const int tx = tid & 15;       // n = tx*4
    const int ty = tid >> 4;       // m = ty*4  (0..7 -> 32 rows)

    float acc[4][4] = {};

    for (int kt = k0; kt < k0 + 512; kt += 32) {
        // A tile: 32 rows x 32 k -> 256 float4, 2 per thread, transposed store
#pragma unroll
        for (int l = 0; l < 2; l++) {
            int li  = tid + l * 128;
            int row = li >> 3;
            int c4  = li & 7;
            float4 a = *(const float4*)(x + (size_t)(m0 + row) * DD + kt + c4 * 4);
            As[c4 * 4 + 0][row] = a.x;
            As[c4 * 4 + 1][row] = a.y;
            As[c4 * 4 + 2][row] = a.z;
            As[c4 * 4 + 3][row] = a.w;
        }
        // B tile: 32 k x 64 n -> 512 float4, 4 per thread
#pragma unroll
        for (int l = 0; l < 4; l++) {
            int li  = tid + l * 128;
            int row = li >> 4;
            int c4  = li & 15;
            *(float4*)(&Bs[row][c4 * 4]) =
                *(const float4*)(W + (size_t)(kt + row) * RR + c4 * 4);
        }
        __syncthreads();
#pragma unroll
        for (int k = 0; k < 32; k++) {
            float4 a = *(const float4*)(&As[k][ty * 4]);
            float4 b = *(const float4*)(&Bs[k][tx * 4]);
            acc[0][0] = fmaf(a.x, b.x, acc[0][0]); acc[0][1] = fmaf(a.x, b.y, acc[0][1]);
            acc[0][2] = fmaf(a.x, b.z, acc[0][2]); acc[0][3] = fmaf(a.x, b.w, acc[0][3]);
            acc[1][0] = fmaf(a.y, b.x, acc[1][0]); acc[1][1] = fmaf(a.y, b.y, acc[1][1]);
            acc[1][2] = fmaf(a.y, b.z, acc[1][2]); acc[1][3] = fmaf(a.y, b.w, acc[1][3]);
            acc[2][0] = fmaf(a.z, b.x, acc[2][0]); acc[2][1] = fmaf(a.z, b.y, acc[2][1]);
            acc[2][2] = fmaf(a.z, b.z, acc[2][2]); acc[2][3] = fmaf(a.z, b.w, acc[2][3]);
            acc[3][0] = fmaf(a.w, b.x, acc[3][0]); acc[3][1] = fmaf(a.w, b.y, acc[3][1]);
            acc[3][2] = fmaf(a.w, b.z, acc[3][2]); acc[3][3] = fmaf(a.w, b.w, acc[3][3]);
        }
        __syncthreads();
    }
#pragma unroll
    for (int i = 0; i < 4; i++) {
        int row = m0 + ty * 4 + i;
        int col = tx * 4;
        float4 o;
        if (ksp == 0) {
            o.x = acc[i][0] + bias[col];
            o.y = acc[i][1] + bias[col + 1];
            o.z = acc[i][2] + bias[col + 2];
            o.w = acc[i][3] + bias[col + 3];
        } else {
            o.x = acc[i][0]; o.y = acc[i][1]; o.z = acc[i][2]; o.w = acc[i][3];
        }
        *(float4*)(Cout + (size_t)row * RR + col) = o;
    }
}

// ---------------------------------------------------------------------------
// MEGA kernel: 128 blocks x 1024 threads, 16 samples/block, one wave.
// Warp-specialized: warps 0-15 compute, warps 16-31 stream W1n/W2n stores.
// ---------------------------------------------------------------------------
#define CS 16
#define O_W1S   0
#define O_W2S   16384
#define O_KX    33024
#define O_VX    34048
#define O_QX    35072
#define O_EK    36096
#define O_LNG   37120
#define O_LNB   37184
#define O_HPRE  37248
#define O_HV    41344
#define O_DHP   45440
#define O_ORR   49536
#define O_DOR   50560
#define O_ZL    51584
#define O_RED   52608
#define O_SCE   52736
#define O_SCQ   52752
#define O_SCH   52768
#define MEGA_FLOATS 52784
#define MEGA_BYTES  (MEGA_FLOATS * 4)

#define BAR_COMPUTE() asm volatile("bar.sync 1, 512;" ::: "memory")

__global__ void __launch_bounds__(1024, 1) mega_kernel(
    const float* __restrict__ W1, const float* __restrict__ W2,
    const float* __restrict__ Wo, const float* __restrict__ bo,
    const float* __restrict__ ln_g, const float* __restrict__ ln_b,
    float* __restrict__ outp)
{
    extern __shared__ float sm[];
    float* W1s  = sm + O_W1S;    // [64][256]
    float* W2s  = sm + O_W2S;    // [256][65]
    float* KX   = sm + O_KX;     // [16][64]
    float* VX   = sm + O_VX;
    float* QX   = sm + O_QX;
    float* EK   = sm + O_EK;
    float* LNG  = sm + O_LNG;
    float* LNB  = sm + O_LNB;
    float* HPRE = sm + O_HPRE;   // [16][256] (becomes H2)
    float* HV   = sm + O_HV;     // [16][256]
    float* DHP  = sm + O_DHP;    // [16][256]
    float* ORR  = sm + O_ORR;    // [16][64]
    float* DOR  = sm + O_DOR;    // [16][64]
    float* ZL   = sm + O_ZL;     // [16][64]
    float* RED  = sm + O_RED;    // [16][8]
    float* SC_ETA = sm + O_SCE;
    float* SC_QK  = sm + O_SCQ;
    float* SC_HH  = sm + O_SCH;

    const int tid  = threadIdx.x;
    const int b0   = blockIdx.x * CS;
    const int lane = tid & 31;
    const int wrp  = tid >> 5;   // 0..31

    // ================= P0: stage =================
#pragma unroll
    for (int l = 0; l < 4; l++) {
        int i = (tid + l * 1024) * 4;
        *(float4*)(W1s + i) = __ldg((const float4*)(W1 + i));
    }
#pragma unroll
    for (int l = 0; l < 4; l++) {
        int i4 = tid + l * 1024;
        int idx = i4 * 4;
        int ii = idx >> 6, rr2 = idx & 63;
        float4 w = __ldg((const float4*)(W2 + idx));
        float* dst = W2s + ii * 65 + rr2;
        dst[0] = w.x; dst[1] = w.y; dst[2] = w.z; dst[3] = w.w;
    }
    if (tid < 768) {
        int seg = tid >> 8, off = tid & 255;
        const float4* p0; const float4* p1; float* dst;
        if (seg == 0)      { p0 = (const float4*)(g_K + (size_t)b0 * 64); p1 = (const float4*)(g_K2 + (size_t)b0 * 64); dst = KX; }
        else if (seg == 1) { p0 = (const float4*)(g_V + (size_t)b0 * 64); p1 = (const float4*)(g_V2 + (size_t)b0 * 64); dst = VX; }
        else               { p0 = (const float4*)(g_Q + (size_t)b0 * 64); p1 = (const float4*)(g_Q2 + (size_t)b0 * 64); dst = QX; }
        float4 a = p0[off], b = p1[off];
        float4 o; o.x = a.x + b.x; o.y = a.y + b.y; o.z = a.z + b.z; o.w = a.w + b.w;
        *(float4*)(dst + off * 4) = o;
    }
    if (tid < 64) { LNG[tid] = ln_g[tid]; LNB[tid] = ln_b[tid]; }
    if (tid >= 64 && tid < 64 + CS) SC_ETA[tid - 64] = g_eta[b0 + tid - 64];
    __syncthreads();

    EK[tid] = SC_ETA[tid >> 6] * KX[tid];

    // ================= P1: hpre = k@W1, hv = gelu (all warps) =============
    {
        const int c  = tid & 255;
        const int sg = (tid >> 8) * 4;
        float acc[4] = {};
#pragma unroll 4
        for (int r = 0; r < 64; r++) {
            float w = W1s[r * 256 + c];
#pragma unroll
            for (int j = 0; j < 4; j++)
                acc[j] = fmaf(w, KX[(sg + j) * 64 + r], acc[j]);
        }
#pragma unroll
        for (int j = 0; j < 4; j++) {
            int s = sg + j;
            float y, dy;
            gelu_fd(acc[j], &y, &dy);
            HPRE[s * 256 + c] = acc[j];
            HV[s * 256 + c]   = y;
        }
    }
    __syncthreads();

    // ================= P2: o = h@W2 (all warps) =================
    {
        const int r = tid & 63, sq = tid >> 6;
        float acc = 0.f;
#pragma unroll 8
        for (int i = 0; i < 256; i++)
            acc = fmaf(W2s[i * 65 + r], HV[sq * 256 + i], acc);
        ORR[sq * 64 + r] = acc;
    }
    __syncthreads();

    // ================= P3: LN fwd + loss + LN bwd + qk (warps 0-15) =======
    if (wrp < CS) {
        int s = wrp;
        float o0 = ORR[s * 64 + lane], o1 = ORR[s * 64 + lane + 32];
        float mu = wredsum(o0 + o1) * (1.f / 64.f);
        float d0 = o0 - mu, d1 = o1 - mu;
        float var = wredsum(d0 * d0 + d1 * d1) * (1.f / 64.f);
        float sf = rsqrtf(var + 1e-6f);
        float n0 = d0 * sf, n1 = d1 * sf;
        float g0 = LNG[lane], g1 = LNG[lane + 32];
        float k0 = KX[s * 64 + lane], k1 = KX[s * 64 + lane + 32];
        float pred0 = k0 + n0 * g0 + LNB[lane];
        float pred1 = k1 + n1 * g1 + LNB[lane + 32];
        float e0 = pred0 - VX[s * 64 + lane], e1 = pred1 - VX[s * 64 + lane + 32];
        float loss = wredsum(e0 * e0 + e1 * e1) * (1.f / 64.f);
        float dn0 = e0 * (2.f / 64.f) * g0;
        float dn1 = e1 * (2.f / 64.f) * g1;
        float m1 = wredsum(dn0 + dn1) * (1.f / 64.f);
        float m2 = wredsum(dn0 * n0 + dn1 * n1) * (1.f / 64.f);
        DOR[s * 64 + lane]      = sf * (dn0 - m1 - n0 * m2);
        DOR[s * 64 + lane + 32] = sf * (dn1 - m1 - n1 * m2);
        float qk = wredsum(QX[s * 64 + lane] * k0 + QX[s * 64 + lane + 32] * k1);
        if (lane == 0) {
            SC_QK[s] = qk;
            outp[OFF_LOSS + b0 + s] = loss;
        }
    }
    __syncthreads();

    // ============ REGION 1: store warps drain W2n  ||  compute warps P4 ====
    if (wrp >= CS) {
        // W2n store: one warp per sample. W2n[s][i][r] = W2[i][r] - eta*hv[i]*dor[r]
        const int s = wrp - CS;
        const int r4 = lane & 15;
        const int ib = lane >> 4;
        const float eta_s = SC_ETA[s];
        const float4 d = *(const float4*)(DOR + s * 64 + r4 * 4);
        const float* hvrow = HV + s * 256;
        float* dst = outp + OFF_W2 + (size_t)(b0 + s) * 16384;
#pragma unroll 4
        for (int it = 0; it < 128; it++) {
            int i = ib + it * 2;
            int rem = i * 16 + r4;
            float4 w = __ldg((const float4*)W2 + rem);
            float sc = eta_s * hvrow[i];
            float4 ov;
            ov.x = w.x - sc * d.x;
            ov.y = w.y - sc * d.y;
            ov.z = w.z - sc * d.z;
            ov.w = w.w - sc * d.w;
            *(float4*)(dst + rem * 4) = ov;
        }
    } else {
        // P4 on 512 threads: c = tid&255, 8 samples per 256-thread group
        const int c  = tid & 255;
        const int sg = (tid >> 8) * 8;
        float acc[8];
#pragma unroll
        for (int j = 0; j < 8; j++) acc[j] = 0.f;
#pragma unroll 4
        for (int r = 0; r < 64; r++) {
            float w = W2s[c * 65 + r];
#pragma unroll
            for (int j = 0; j < 8; j++)
                acc[j] = fmaf(w, DOR[(sg + j) * 64 + r], acc[j]);
        }
#pragma unroll
        for (int j = 0; j < 8; j++) {
            int s = sg + j;
            float y, dy;
            gelu_fd(HPRE[s * 256 + c], &y, &dy);
            DHP[s * 256 + c] = acc[j] * dy;
        }
        // reuse acc for q@W1
#pragma unroll
        for (int j = 0; j < 8; j++) acc[j] = 0.f;
#pragma unroll 4
        for (int r = 0; r < 64; r++) {
            float w = W1s[r * 256 + c];
#pragma unroll
            for (int j = 0; j < 8; j++)
                acc[j] = fmaf(w, QX[(sg + j) * 64 + r], acc[j]);
        }
#pragma unroll
        for (int j = 0; j < 8; j++) {
            int s = sg + j;
            float eqk = SC_ETA[s] * SC_QK[s];
            float y, dyt;
            gelu_fd(acc[j] - eqk * DHP[s * 256 + c], &y, &dyt);
            HPRE[s * 256 + c] = y;           // H2 overwrites HPRE
            float p = wredsum(y * HV[s * 256 + c]);
            if (lane == 0) RED[s * 8 + (wrp & 7)] = p;
        }
    }
    __syncthreads();   // A: DHP/H2/RED visible to everyone; W2n fully issued

    // ============ REGION 2: store warps drain W1n || compute P5-P7 =========
    if (wrp >= CS) {
        // W1n store: one warp per sample. W1n[s][r][i] = W1[r][i] - ek[r]*dhp[i]
        const int s = wrp - CS;
        const float4 d0 = *(const float4*)(DHP + s * 256 + lane * 4);
        const float4 d1 = *(const float4*)(DHP + s * 256 + (lane + 32) * 4);
        const float* ekrow = EK + s * 64;
        float* dst = outp + OFF_W1 + (size_t)(b0 + s) * 16384;
#pragma unroll 4
        for (int r = 0; r < 64; r++) {
            float sc = ekrow[r];
            int rem0 = r * 64 + lane;
            int rem1 = rem0 + 32;
            float4 w0 = __ldg((const float4*)W1 + rem0);
            float4 w1 = __ldg((const float4*)W1 + rem1);
            float4 ov;
            ov.x = w0.x - sc * d0.x;
            ov.y = w0.y - sc * d0.y;
            ov.z = w0.z - sc * d0.z;
            ov.w = w0.w - sc * d0.w;
            *(float4*)(dst + rem0 * 4) = ov;
            ov.x = w1.x - sc * d1.x;
            ov.y = w1.y - sc * d1.y;
            ov.z = w1.z - sc * d1.z;
            ov.w = w1.w - sc * d1.w;
            *(float4*)(dst + rem1 * 4) = ov;
        }
        // store warps hit NO further barrier; fall through to kernel end
    } else {
        // SC_HH
        if (tid < CS) {
            float hh = 0.f;
#pragma unroll
            for (int w = 0; w < 8; w++) hh += RED[tid * 8 + w];
            SC_HH[tid] = hh;
        }
        BAR_COMPUTE();

        // P5: o2 = h2@W2 - eta*hh*do  (512 threads, 2 sq per thread)
        {
            const int r = tid & 63, sq = tid >> 6;   // sq in [0,8)
            float acc0 = 0.f, acc1 = 0.f;
#pragma unroll 8
            for (int i = 0; i < 256; i++) {
                float w = W2s[i * 65 + r];
                acc0 = fmaf(w, HPRE[sq * 256 + i], acc0);
                acc1 = fmaf(w, HPRE[(sq + 8) * 256 + i], acc1);
            }
            ORR[sq * 64 + r]       = acc0 - SC_ETA[sq]     * SC_HH[sq]     * DOR[sq * 64 + r];
            ORR[(sq + 8) * 64 + r] = acc1 - SC_ETA[sq + 8] * SC_HH[sq + 8] * DOR[(sq + 8) * 64 + r];
        }
        BAR_COMPUTE();

        // P6: z = q + LN(o2)  (warp = sample)
        {
            int s = wrp;
            float o0 = ORR[s * 64 + lane], o1 = ORR[s * 64 + lane + 32];
            float mu = wredsum(o0 + o1) * (1.f / 64.f);
            float d0 = o0 - mu, d1 = o1 - mu;
            float var = wredsum(d0 * d0 + d1 * d1) * (1.f / 64.f);
            float sf = rsqrtf(var + 1e-6f);
            ZL[s * 64 + lane]      = QX[s * 64 + lane]      + (d0 * sf) * LNG[lane]      + LNB[lane];
            ZL[s * 64 + lane + 32] = QX[s * 64 + lane + 32] + (d1 * sf) * LNG[lane + 32] + LNB[lane + 32];
        }
        BAR_COMPUTE();

        // P7: out = z @ Wo + bo  (512 threads, 2 column passes)
        {
            const int sg4 = (tid >> 7) * 4;        // 4 rows per 128-thread group
            const int cb  = (tid & 127) * 4;
#pragma unroll
            for (int nc = 0; nc < 2; nc++) {
                const int n0 = cb + nc * 512;
                float a0[4] = {}, a1[4] = {}, a2[4] = {}, a3[4] = {};
#pragma unroll 4
                for (int r = 0; r < 64; r++) {
                    float4 w = __ldg((const float4*)(Wo + (size_t)r * 1024 + n0));
                    float z0 = ZL[(sg4 + 0) * 64 + r];
                    float z1 = ZL[(sg4 + 1) * 64 + r];
                    float z2 = ZL[(sg4 + 2) * 64 + r];
                    float z3 = ZL[(sg4 + 3) * 64 + r];
                    a0[0] = fmaf(z0, w.x, a0[0]); a0[1] = fmaf(z0, w.y, a0[1]);
                    a0[2] = fmaf(z0, w.z, a0[2]); a0[3] = fmaf(z0, w.w, a0[3]);
                    a1[0] = fmaf(z1, w.x, a1[0]); a1[1] = fmaf(z1, w.y, a1[1]);
                    a1[2] = fmaf(z1, w.z, a1[2]); a1[3] = fmaf(z1, w.w, a1[3]);
                    a2[0] = fmaf(z2, w.x, a2[0]); a2[1] = fmaf(z2, w.y, a2[1]);
                    a2[2] = fmaf(z2, w.z, a2[2]); a2[3] = fmaf(z2, w.w, a2[3]);
                    a3[0] = fmaf(z3, w.x, a3[0]); a3[1] = fmaf(z3, w.y, a3[1]);
                    a3[2] = fmaf(z3, w.z, a3[2]); a3[3] = fmaf(z3, w.w, a3[3]);
                }
                float4 bb = __ldg((const float4*)(bo + n0));
                float4 ov;
                ov.x = a0[0] + bb.x; ov.y = a0[1] + bb.y; ov.z = a0[2] + bb.z; ov.w = a0[3] + bb.w;
                *(float4*)(outp + OFF_OUT + (size_t)(b0 + sg4 + 0) * 1024 + n0) = ov;
                ov.x = a1[0] + bb.x; ov.y = a1[1] + bb.y; ov.z = a1[2] + bb.z; ov.w = a1[3] + bb.w;
                *(float4*)(outp + OFF_OUT + (size_t)(b0 + sg4 + 1) * 1024 + n0) = ov;
                ov.x = a2[0] + bb.x; ov.y = a2[1] + bb.y; ov.z = a2[2] + bb.z; ov.w = a2[3] + bb.w;
                *(float4*)(outp + OFF_OUT + (size_t)(b0 + sg4 + 2) * 1024 + n0) = ov;
                ov.x = a3[0] + bb.x; ov.y = a3[1] + bb.y; ov.z = a3[2] + bb.z; ov.w = a3[3] + bb.w;
                *(float4*)(outp + OFF_OUT + (size_t)(b0 + sg4 + 3) * 1024 + n0) = ov;
            }
        }
    }
}

// ---------------------------------------------------------------------------
extern "C" void kernel_launch(void* const* d_in, const int* in_sizes, int n_in,
                              void* d_out, int out_size)
{
    const float* x    = (const float*)d_in[0];
    const float* Wk   = (const float*)d_in[1];
    const float* bk   = (const float*)d_in[2];
    const float* Wv   = (const float*)d_in[3];
    const float* bv   = (const float*)d_in[4];
    const float* Wq   = (const float*)d_in[5];
    const float* bq   = (const float*)d_in[6];
    const float* Wo   = (const float*)d_in[7];
    const float* bo   = (const float*)d_in[8];
    const float* ln_g = (const float*)d_in[9];
    const float* ln_b = (const float*)d_in[10];
    const float* lr_w = (const float*)d_in[11];
    const float* lr_b = (const float*)d_in[12];
    const float* W1   = (const float*)d_in[13];
    const float* W2   = (const float*)d_in[14];
    float* outp = (float*)d_out;

    cudaFuncSetAttribute(mega_kernel,
                         cudaFuncAttributeMaxDynamicSharedMemorySize, MEGA_BYTES);

    proj_eta_kernel<<<448, 128>>>(x, Wk, bk, Wv, bv, Wq, bq, lr_w, lr_b);
    mega_kernel<<<128, 1024, MEGA_BYTES>>>(W1, W2, Wo, bo, ln_g, ln_b, outp);
}

// round 11
// speedup vs baseline: 1.6033x; 1.0808x over previous
#include <cuda_runtime.h>
#include <math.h>

#define BB 2048
#define DD 1024
#define RR 64
#define HH 256

// output layout: [out (B*1024)] [W1n (B*64*256)] [W2n (B*256*64)] [ssl_loss (B)]
#define OFF_OUT  0ull
#define OFF_W1   (2048ull*1024ull)
#define OFF_W2   (OFF_W1 + 2048ull*16384ull)
#define OFF_LOSS (OFF_W2 + 2048ull*16384ull)

__device__ float g_K [BB*RR];
__device__ float g_V [BB*RR];
__device__ float g_Q [BB*RR];
__device__ float g_K2[BB*RR];
__device__ float g_V2[BB*RR];
__device__ float g_Q2[BB*RR];
__device__ float g_eta[BB];

static __device__ __forceinline__ float wredsum(float v) {
#pragma unroll
    for (int o = 16; o; o >>= 1) v += __shfl_xor_sync(0xffffffffu, v, o);
    return v;
}

// fast tanh: 1 - 2/(e^{2x}+1); __expf/__fdividef are MUFU-based, rel err ~1e-6
static __device__ __forceinline__ float tanh_fast(float x) {
    float e = __expf(2.0f * x);
    return 1.0f - __fdividef(2.0f, e + 1.0f);
}

static __device__ __forceinline__ void gelu_fd(float x, float* y, float* dy) {
    const float c = 0.7978845608028654f;
    const float a = 0.044715f;
    float x2 = x * x;
    float u = c * (x + a * x * x2);
    float t = tanh_fast(u);
    float half1pt = 0.5f * (1.f + t);
    *y  = x * half1pt;
    *dy = half1pt + 0.5f * x * (1.f - t * t) * c * (1.f + 3.f * a * x2);
}

// ---------------------------------------------------------------------------
// proj + eta (unchanged from round 10: 448 x 128-thread blocks)
// ---------------------------------------------------------------------------
__global__ void __launch_bounds__(128) proj_eta_kernel(
    const float* __restrict__ x,
    const float* __restrict__ Wk, const float* __restrict__ bk,
    const float* __restrict__ Wv, const float* __restrict__ bv,
    const float* __restrict__ Wq, const float* __restrict__ bq,
    const float* __restrict__ lr_w, const float* __restrict__ lr_b)
{
    const int tid = threadIdx.x;
    const int lane = tid & 31;
    const int wrp = tid >> 5;
    const int bid = blockIdx.x;

    if (bid >= 384) {
        int rbase = (bid - 384) * 32 + wrp * 8;
#pragma unroll
        for (int jj = 0; jj < 8; jj++) {
            int row = rbase + jj;
            const float* xr = x + (size_t)row * DD;
            float s = 0.f;
#pragma unroll 8
            for (int j = lane; j < DD; j += 32) s = fmaf(xr[j], lr_w[j], s);
            s = wredsum(s);
            if (lane == 0) g_eta[row] = 0.1f / (1.f + expf(-(s + lr_b[0])));
        }
        return;
    }

    const int mat = bid / 128;
    const int rem = bid % 128;
    const int ksp = rem & 1;
    const int m0  = (rem >> 1) * 32;
    const int k0  = ksp * 512;

    const float* W    = (mat == 0) ? Wk : (mat == 1) ? Wv : Wq;
    const float* bias = (mat == 0) ? bk : (mat == 1) ? bv : bq;
    float* Cout = (ksp == 0) ? ((mat == 0) ? g_K : (mat == 1) ? g_V : g_Q)
                             : ((mat == 0) ? g_K2 : (mat == 1) ? g_V2 : g_Q2);

    __shared__ float As[32][36];
    __shared__ float Bs[32][64];

    const int tx = tid & 15;
    const int ty = tid >> 4;

    float acc[4][4] = {};

    for (int kt = k0; kt < k0 + 512; kt += 32) {
#pragma unroll
        for (int l = 0; l < 2; l++) {
            int li  = tid + l * 128;
            int row = li >> 3;
            int c4  = li & 7;
            float4 a = *(const float4*)(x + (size_t)(m0 + row) * DD + kt + c4 * 4);
            As[c4 * 4 + 0][row] = a.x;
            As[c4 * 4 + 1][row] = a.y;
            As[c4 * 4 + 2][row] = a.z;
            As[c4 * 4 + 3][row] = a.w;
        }
#pragma unroll
        for (int l = 0; l < 4; l++) {
            int li  = tid + l * 128;
            int row = li >> 4;
            int c4  = li & 15;
            *(float4*)(&Bs[row][c4 * 4]) =
                *(const float4*)(W + (size_t)(kt + row) * RR + c4 * 4);
        }
        __syncthreads();
#pragma unroll
        for (int k = 0; k < 32; k++) {
            float4 a = *(const float4*)(&As[k][ty * 4]);
            float4 b = *(const float4*)(&Bs[k][tx * 4]);
            acc[0][0] = fmaf(a.x, b.x, acc[0][0]); acc[0][1] = fmaf(a.x, b.y, acc[0][1]);
            acc[0][2] = fmaf(a.x, b.z, acc[0][2]); acc[0][3] = fmaf(a.x, b.w, acc[0][3]);
            acc[1][0] = fmaf(a.y, b.x, acc[1][0]); acc[1][1] = fmaf(a.y, b.y, acc[1][1]);
            acc[1][2] = fmaf(a.y, b.z, acc[1][2]); acc[1][3] = fmaf(a.y, b.w, acc[1][3]);
            acc[2][0] = fmaf(a.z, b.x, acc[2][0]); acc[2][1] = fmaf(a.z, b.y, acc[2][1]);
            acc[2][2] = fmaf(a.z, b.z, acc[2][2]); acc[2][3] = fmaf(a.z, b.w, acc[2][3]);
            acc[3][0] = fmaf(a.w, b.x, acc[3][0]); acc[3][1] = fmaf(a.w, b.y, acc[3][1]);
            acc[3][2] = fmaf(a.w, b.z, acc[3][2]); acc[3][3] = fmaf(a.w, b.w, acc[3][3]);
        }
        __syncthreads();
    }
#pragma unroll
    for (int i = 0; i < 4; i++) {
        int row = m0 + ty * 4 + i;
        int col = tx * 4;
        float4 o;
        if (ksp == 0) {
            o.x = acc[i][0] + bias[col];
            o.y = acc[i][1] + bias[col + 1];
            o.z = acc[i][2] + bias[col + 2];
            o.w = acc[i][3] + bias[col + 3];
        } else {
            o.x = acc[i][0]; o.y = acc[i][1]; o.z = acc[i][2]; o.w = acc[i][3];
        }
        *(float4*)(Cout + (size_t)row * RR + col) = o;
    }
}

// ---------------------------------------------------------------------------
// MEGA kernel: 128 blocks x 1024 threads, 16 samples/block.
// float4-widened phases; warps 16-31 stream stores in regions 1/2; P7 all-warp.
// W2s stride = 68 (float4 rows; column access (4i+r)%32 conflict-free).
// ---------------------------------------------------------------------------
#define CS 16
#define O_W1S   0
#define O_W2S   16384
#define O_KX    33792
#define O_VX    34816
#define O_QX    35840
#define O_EK    36864
#define O_LNG   37888
#define O_LNB   37952
#define O_HPRE  38016
#define O_HV    42112
#define O_GDY   46208
#define O_DHP   50304
#define O_ORR   54400
#define O_DOR   55424
#define O_ZL    56448
#define O_RED   57472
#define O_SCE   57600
#define O_SCQ   57616
#define O_SCH   57632
#define MEGA_FLOATS 57648
#define MEGA_BYTES  (MEGA_FLOATS * 4)

#define BAR_COMPUTE() asm volatile("bar.sync 1, 512;" ::: "memory")

__global__ void __launch_bounds__(1024, 1) mega_kernel(
    const float* __restrict__ W1, const float* __restrict__ W2,
    const float* __restrict__ Wo, const float* __restrict__ bo,
    const float* __restrict__ ln_g, const float* __restrict__ ln_b,
    float* __restrict__ outp)
{
    extern __shared__ float sm[];
    float* W1s  = sm + O_W1S;    // [64][256]
    float* W2s  = sm + O_W2S;    // [256][68]
    float* KX   = sm + O_KX;
    float* VX   = sm + O_VX;
    float* QX   = sm + O_QX;
    float* EK   = sm + O_EK;
    float* LNG  = sm + O_LNG;
    float* LNB  = sm + O_LNB;
    float* HPRE = sm + O_HPRE;   // [16][256] (becomes H2)
    float* HV   = sm + O_HV;     // [16][256] (P5 partial scratch later)
    float* GDY  = sm + O_GDY;    // [16][256] gelu'(hpre)
    float* DHP  = sm + O_DHP;    // [16][256] (P2 partial scratch earlier)
    float* ORR  = sm + O_ORR;
    float* DOR  = sm + O_DOR;
    float* ZL   = sm + O_ZL;
    float* RED  = sm + O_RED;    // [16][8]
    float* SC_ETA = sm + O_SCE;
    float* SC_QK  = sm + O_SCQ;
    float* SC_HH  = sm + O_SCH;

    const int tid  = threadIdx.x;
    const int b0   = blockIdx.x * CS;
    const int lane = tid & 31;
    const int wrp  = tid >> 5;

    // ================= P0: stage =================
#pragma unroll
    for (int l = 0; l < 4; l++) {
        int i = (tid + l * 1024) * 4;
        *(float4*)(W1s + i) = __ldg((const float4*)(W1 + i));
    }
#pragma unroll
    for (int l = 0; l < 4; l++) {
        int i4 = tid + l * 1024;
        int idx = i4 * 4;
        int ii = idx >> 6, rr2 = idx & 63;
        float4 w = __ldg((const float4*)(W2 + idx));
        *(float4*)(W2s + ii * 68 + rr2) = w;
    }
    if (tid < 768) {
        int seg = tid >> 8, off = tid & 255;
        const float4* p0; const float4* p1; float* dst;
        if (seg == 0)      { p0 = (const float4*)(g_K + (size_t)b0 * 64); p1 = (const float4*)(g_K2 + (size_t)b0 * 64); dst = KX; }
        else if (seg == 1) { p0 = (const float4*)(g_V + (size_t)b0 * 64); p1 = (const float4*)(g_V2 + (size_t)b0 * 64); dst = VX; }
        else               { p0 = (const float4*)(g_Q + (size_t)b0 * 64); p1 = (const float4*)(g_Q2 + (size_t)b0 * 64); dst = QX; }
        float4 a = p0[off], b = p1[off];
        float4 o; o.x = a.x + b.x; o.y = a.y + b.y; o.z = a.z + b.z; o.w = a.w + b.w;
        *(float4*)(dst + off * 4) = o;
    }
    if (tid < 64) { LNG[tid] = ln_g[tid]; LNB[tid] = ln_b[tid]; }
    if (tid >= 64 && tid < 64 + CS) SC_ETA[tid - 64] = g_eta[b0 + tid - 64];
    __syncthreads();

    EK[tid] = SC_ETA[tid >> 6] * KX[tid];

    // ================= P1: hpre = k@W1, hv/gdy = gelu (all warps) =========
    {
        const int c  = tid & 255;
        const int sg = (tid >> 8) * 4;
        float a0 = 0.f, a1 = 0.f, a2 = 0.f, a3 = 0.f;
#pragma unroll
        for (int r4 = 0; r4 < 64; r4 += 4) {
            float w0 = W1s[(r4 + 0) * 256 + c];
            float w1 = W1s[(r4 + 1) * 256 + c];
            float w2 = W1s[(r4 + 2) * 256 + c];
            float w3 = W1s[(r4 + 3) * 256 + c];
            float4 k0 = *(const float4*)(KX + (sg + 0) * 64 + r4);
            float4 k1 = *(const float4*)(KX + (sg + 1) * 64 + r4);
            float4 k2 = *(const float4*)(KX + (sg + 2) * 64 + r4);
            float4 k3 = *(const float4*)(KX + (sg + 3) * 64 + r4);
            a0 = fmaf(w0, k0.x, fmaf(w1, k0.y, fmaf(w2, k0.z, fmaf(w3, k0.w, a0))));
            a1 = fmaf(w0, k1.x, fmaf(w1, k1.y, fmaf(w2, k1.z, fmaf(w3, k1.w, a1))));
            a2 = fmaf(w0, k2.x, fmaf(w1, k2.y, fmaf(w2, k2.z, fmaf(w3, k2.w, a2))));
            a3 = fmaf(w0, k3.x, fmaf(w1, k3.y, fmaf(w2, k3.z, fmaf(w3, k3.w, a3))));
        }
        float acc[4] = {a0, a1, a2, a3};
#pragma unroll
        for (int j = 0; j < 4; j++) {
            int s = sg + j;
            float y, dy;
            gelu_fd(acc[j], &y, &dy);
            HPRE[s * 256 + c] = acc[j];
            HV[s * 256 + c]   = y;
            GDY[s * 256 + c]  = dy;
        }
    }
    __syncthreads();

    // ================= P2: o = h@W2 (all warps, i-split x4) ===============
    {
        const int r  = tid & 63;
        const int ic = (tid >> 6) & 3;
        const int sg = (tid >> 8) * 4;
        const int ib = ic * 64;
        float a0 = 0.f, a1 = 0.f, a2 = 0.f, a3 = 0.f;
#pragma unroll
        for (int ii = 0; ii < 64; ii += 4) {
            int i = ib + ii;
            float w0 = W2s[(i + 0) * 68 + r];
            float w1 = W2s[(i + 1) * 68 + r];
            float w2 = W2s[(i + 2) * 68 + r];
            float w3 = W2s[(i + 3) * 68 + r];
            float4 h0 = *(const float4*)(HV + (sg + 0) * 256 + i);
            float4 h1 = *(const float4*)(HV + (sg + 1) * 256 + i);
            float4 h2 = *(const float4*)(HV + (sg + 2) * 256 + i);
            float4 h3 = *(const float4*)(HV + (sg + 3) * 256 + i);
            a0 = fmaf(w0, h0.x, fmaf(w1, h0.y, fmaf(w2, h0.z, fmaf(w3, h0.w, a0))));
            a1 = fmaf(w0, h1.x, fmaf(w1, h1.y, fmaf(w2, h1.z, fmaf(w3, h1.w, a1))));
            a2 = fmaf(w0, h2.x, fmaf(w1, h2.y, fmaf(w2, h2.z, fmaf(w3, h2.w, a2))));
            a3 = fmaf(w0, h3.x, fmaf(w1, h3.y, fmaf(w2, h3.z, fmaf(w3, h3.w, a3))));
        }
        DHP[ic * 1024 + (sg + 0) * 64 + r] = a0;
        DHP[ic * 1024 + (sg + 1) * 64 + r] = a1;
        DHP[ic * 1024 + (sg + 2) * 64 + r] = a2;
        DHP[ic * 1024 + (sg + 3) * 64 + r] = a3;
    }
    __syncthreads();
    {
        int s = tid >> 6, rr = tid & 63;
        int o = s * 64 + rr;
        ORR[o] = DHP[o] + DHP[1024 + o] + DHP[2048 + o] + DHP[3072 + o];
    }
    __syncthreads();

    // ================= P3: LN fwd + loss + LN bwd + qk (warps 0-15) =======
    if (wrp < CS) {
        int s = wrp;
        float o0 = ORR[s * 64 + lane], o1 = ORR[s * 64 + lane + 32];
        float mu = wredsum(o0 + o1) * (1.f / 64.f);
        float d0 = o0 - mu, d1 = o1 - mu;
        float var = wredsum(d0 * d0 + d1 * d1) * (1.f / 64.f);
        float sf = rsqrtf(var + 1e-6f);
        float n0 = d0 * sf, n1 = d1 * sf;
        float g0 = LNG[lane], g1 = LNG[lane + 32];
        float k0 = KX[s * 64 + lane], k1 = KX[s * 64 + lane + 32];
        float pred0 = k0 + n0 * g0 + LNB[lane];
        float pred1 = k1 + n1 * g1 + LNB[lane + 32];
        float e0 = pred0 - VX[s * 64 + lane], e1 = pred1 - VX[s * 64 + lane + 32];
        float loss = wredsum(e0 * e0 + e1 * e1) * (1.f / 64.f);
        float dn0 = e0 * (2.f / 64.f) * g0;
        float dn1 = e1 * (2.f / 64.f) * g1;
        float m1 = wredsum(dn0 + dn1) * (1.f / 64.f);
        float m2 = wredsum(dn0 * n0 + dn1 * n1) * (1.f / 64.f);
        DOR[s * 64 + lane]      = sf * (dn0 - m1 - n0 * m2);
        DOR[s * 64 + lane + 32] = sf * (dn1 - m1 - n1 * m2);
        float qk = wredsum(QX[s * 64 + lane] * k0 + QX[s * 64 + lane + 32] * k1);
        if (lane == 0) {
            SC_QK[s] = qk;
            outp[OFF_LOSS + b0 + s] = loss;
        }
    }
    __syncthreads();

    // ============ REGION 1: store warps drain W2n || compute warps P4 =====
    if (wrp >= CS) {
        const int s = wrp - CS;
        const int r4 = lane & 15;
        const int ib = lane >> 4;
        const float eta_s = SC_ETA[s];
        const float4 d = *(const float4*)(DOR + s * 64 + r4 * 4);
        const float* hvrow = HV + s * 256;
        float* dst = outp + OFF_W2 + (size_t)(b0 + s) * 16384;
#pragma unroll 4
        for (int it = 0; it < 128; it++) {
            int i = ib + it * 2;
            int rem = i * 16 + r4;
            float4 w = __ldg((const float4*)W2 + rem);
            float sc = eta_s * hvrow[i];
            float4 ov;
            ov.x = w.x - sc * d.x;
            ov.y = w.y - sc * d.y;
            ov.z = w.z - sc * d.z;
            ov.w = w.w - sc * d.w;
            *(float4*)(dst + rem * 4) = ov;
        }
    } else {
        const int c = tid & 255;
        const int sgh = (tid >> 8) * 8;
        float acc[8];
#pragma unroll
        for (int j = 0; j < 8; j++) acc[j] = 0.f;
#pragma unroll
        for (int r4 = 0; r4 < 64; r4 += 4) {
            float4 w4 = *(const float4*)(W2s + c * 68 + r4);
#pragma unroll
            for (int j = 0; j < 8; j++) {
                float4 d4 = *(const float4*)(DOR + (sgh + j) * 64 + r4);
                acc[j] = fmaf(w4.x, d4.x, fmaf(w4.y, d4.y,
                         fmaf(w4.z, d4.z, fmaf(w4.w, d4.w, acc[j]))));
            }
        }
#pragma unroll
        for (int j = 0; j < 8; j++) {
            int s = sgh + j;
            acc[j] *= GDY[s * 256 + c];
            DHP[s * 256 + c] = acc[j];
        }
        // reuse acc for q@W1
#pragma unroll
        for (int j = 0; j < 8; j++) acc[j] = 0.f;
#pragma unroll
        for (int r4 = 0; r4 < 64; r4 += 4) {
            float w0 = W1s[(r4 + 0) * 256 + c];
            float w1 = W1s[(r4 + 1) * 256 + c];
            float w2 = W1s[(r4 + 2) * 256 + c];
            float w3 = W1s[(r4 + 3) * 256 + c];
#pragma unroll
            for (int j = 0; j < 8; j++) {
                float4 q4 = *(const float4*)(QX + (sgh + j) * 64 + r4);
                acc[j] = fmaf(w0, q4.x, fmaf(w1, q4.y,
                         fmaf(w2, q4.z, fmaf(w3, q4.w, acc[j]))));
            }
        }
#pragma unroll
        for (int j = 0; j < 8; j++) {
            int s = sgh + j;
            float eqk = SC_ETA[s] * SC_QK[s];
            float y, dyt;
            gelu_fd(acc[j] - eqk * DHP[s * 256 + c], &y, &dyt);
            HPRE[s * 256 + c] = y;           // H2 overwrites HPRE
            float p = wredsum(y * HV[s * 256 + c]);
            if (lane == 0) RED[s * 8 + (wrp & 7)] = p;
        }
    }
    __syncthreads();   // A

    // ============ REGION 2: store warps drain W1n || compute P5-P6 =========
    if (wrp >= CS) {
        const int s = wrp - CS;
        const float4 d0 = *(const float4*)(DHP + s * 256 + lane * 4);
        const float4 d1 = *(const float4*)(DHP + s * 256 + (lane + 32) * 4);
        const float* ekrow = EK + s * 64;
        float* dst = outp + OFF_W1 + (size_t)(b0 + s) * 16384;
#pragma unroll 4
        for (int r = 0; r < 64; r++) {
            float sc = ekrow[r];
            int rem0 = r * 64 + lane;
            int rem1 = rem0 + 32;
            float4 w0 = __ldg((const float4*)W1 + rem0);
            float4 w1 = __ldg((const float4*)W1 + rem1);
            float4 ov;
            ov.x = w0.x - sc * d0.x;
            ov.y = w0.y - sc * d0.y;
            ov.z = w0.z - sc * d0.z;
            ov.w = w0.w - sc * d0.w;
            *(float4*)(dst + rem0 * 4) = ov;
            ov.x = w1.x - sc * d1.x;
            ov.y = w1.y - sc * d1.y;
            ov.z = w1.z - sc * d1.z;
            ov.w = w1.w - sc * d1.w;
            *(float4*)(dst + rem1 * 4) = ov;
        }
        // no further named barriers; falls to __syncthreads below
    } else {
        if (tid < CS) {
            float hh = 0.f;
#pragma unroll
            for (int w = 0; w < 8; w++) hh += RED[tid * 8 + w];
            SC_HH[tid] = hh;
        }
        // P5 partials: o2 = h2@W2, i-split x4, 8 samples per thread
        {
            const int r  = tid & 63;
            const int ic = (tid >> 6) & 3;
            const int sgh = (tid >> 8) * 8;
            const int ib = ic * 64;
            float acc[8];
#pragma unroll
            for (int j = 0; j < 8; j++) acc[j] = 0.f;
#pragma unroll
            for (int ii = 0; ii < 64; ii += 4) {
                int i = ib + ii;
                float w0 = W2s[(i + 0) * 68 + r];
                float w1 = W2s[(i + 1) * 68 + r];
                float w2 = W2s[(i + 2) * 68 + r];
                float w3 = W2s[(i + 3) * 68 + r];
#pragma unroll
                for (int j = 0; j < 8; j++) {
                    float4 h4 = *(const float4*)(HPRE + (sgh + j) * 256 + i);
                    acc[j] = fmaf(w0, h4.x, fmaf(w1, h4.y,
                             fmaf(w2, h4.z, fmaf(w3, h4.w, acc[j]))));
                }
            }
#pragma unroll
            for (int j = 0; j < 8; j++)
                HV[ic * 1024 + (sgh + j) * 64 + r] = acc[j];   // partials in HV
        }
        BAR_COMPUTE();
        // P5 reduce + correction (2 outputs per thread)
        {
            int s = tid >> 6;      // 0..7
            int rr = tid & 63;
#pragma unroll
            for (int hh2 = 0; hh2 < 2; hh2++) {
                int sr = s + hh2 * 8;
                int o = sr * 64 + rr;
                float v = HV[o] + HV[1024 + o] + HV[2048 + o] + HV[3072 + o];
                ORR[o] = v - SC_ETA[sr] * SC_HH[sr] * DOR[o];
            }
        }
        BAR_COMPUTE();
        // P6: z = q + LN(o2)  (warp = sample)
        {
            int s = wrp;
            float o0 = ORR[s * 64 + lane], o1 = ORR[s * 64 + lane + 32];
            float mu = wredsum(o0 + o1) * (1.f / 64.f);
            float d0 = o0 - mu, d1 = o1 - mu;
            float var = wredsum(d0 * d0 + d1 * d1) * (1.f / 64.f);
            float sf = rsqrtf(var + 1e-6f);
            ZL[s * 64 + lane]      = QX[s * 64 + lane]      + (d0 * sf) * LNG[lane]      + LNB[lane];
            ZL[s * 64 + lane + 32] = QX[s * 64 + lane + 32] + (d1 * sf) * LNG[lane + 32] + LNB[lane + 32];
        }
    }
    __syncthreads();   // B: ZL ready, W1n done

    // ================= P7: out = z @ Wo + bo (ALL 32 warps) ===============
    {
        const int sg4 = (tid >> 8) * 4;
        const int n4  = (tid & 255) * 4;
        float4 A0 = {0.f, 0.f, 0.f, 0.f}, A1 = A0, A2 = A0, A3 = A0;
#pragma unroll
        for (int r4 = 0; r4 < 64; r4 += 4) {
            float4 z0 = *(const float4*)(ZL + (sg4 + 0) * 64 + r4);
            float4 z1 = *(const float4*)(ZL + (sg4 + 1) * 64 + r4);
            float4 z2 = *(const float4*)(ZL + (sg4 + 2) * 64 + r4);
            float4 z3 = *(const float4*)(ZL + (sg4 + 3) * 64 + r4);
            float4 w;
            w = __ldg((const float4*)(Wo + (size_t)(r4 + 0) * 1024 + n4));
            A0.x = fmaf(z0.x, w.x, A0.x); A0.y = fmaf(z0.x, w.y, A0.y); A0.z = fmaf(z0.x, w.z, A0.z); A0.w = fmaf(z0.x, w.w, A0.w);
            A1.x = fmaf(z1.x, w.x, A1.x); A1.y = fmaf(z1.x, w.y, A1.y); A1.z = fmaf(z1.x, w.z, A1.z); A1.w = fmaf(z1.x, w.w, A1.w);
            A2.x = fmaf(z2.x, w.x, A2.x); A2.y = fmaf(z2.x, w.y, A2.y); A2.z = fmaf(z2.x, w.z, A2.z); A2.w = fmaf(z2.x, w.w, A2.w);
            A3.x = fmaf(z3.x, w.x, A3.x); A3.y = fmaf(z3.x, w.y, A3.y); A3.z = fmaf(z3.x, w.z, A3.z); A3.w = fmaf(z3.x, w.w, A3.w);
            w = __ldg((const float4*)(Wo + (size_t)(r4 + 1) * 1024 + n4));
            A0.x = fmaf(z0.y, w.x, A0.x); A0.y = fmaf(z0.y, w.y, A0.y); A0.z = fmaf(z0.y, w.z, A0.z); A0.w = fmaf(z0.y, w.w, A0.w);
            A1.x = fmaf(z1.y, w.x, A1.x); A1.y = fmaf(z1.y, w.y, A1.y); A1.z = fmaf(z1.y, w.z, A1.z); A1.w = fmaf(z1.y, w.w, A1.w);
            A2.x = fmaf(z2.y, w.x, A2.x); A2.y = fmaf(z2.y, w.y, A2.y); A2.z = fmaf(z2.y, w.z, A2.z); A2.w = fmaf(z2.y, w.w, A2.w);
            A3.x = fmaf(z3.y, w.x, A3.x); A3.y = fmaf(z3.y, w.y, A3.y); A3.z = fmaf(z3.y, w.z, A3.z); A3.w = fmaf(z3.y, w.w, A3.w);
            w = __ldg((const float4*)(Wo + (size_t)(r4 + 2) * 1024 + n4));
            A0.x = fmaf(z0.z, w.x, A0.x); A0.y = fmaf(z0.z, w.y, A0.y); A0.z = fmaf(z0.z, w.z, A0.z); A0.w = fmaf(z0.z, w.w, A0.w);
            A1.x = fmaf(z1.z, w.x, A1.x); A1.y = fmaf(z1.z, w.y, A1.y); A1.z = fmaf(z1.z, w.z, A1.z); A1.w = fmaf(z1.z, w.w, A1.w);
            A2.x = fmaf(z2.z, w.x, A2.x); A2.y = fmaf(z2.z, w.y, A2.y); A2.z = fmaf(z2.z, w.z, A2.z); A2.w = fmaf(z2.z, w.w, A2.w);
            A3.x = fmaf(z3.z, w.x, A3.x); A3.y = fmaf(z3.z, w.y, A3.y); A3.z = fmaf(z3.z, w.z, A3.z); A3.w = fmaf(z3.z, w.w, A3.w);
            w = __ldg((const float4*)(Wo + (size_t)(r4 + 3) * 1024 + n4));
            A0.x = fmaf(z0.w, w.x, A0.x); A0.y = fmaf(z0.w, w.y, A0.y); A0.z = fmaf(z0.w, w.z, A0.z); A0.w = fmaf(z0.w, w.w, A0.w);
            A1.x = fmaf(z1.w, w.x, A1.x); A1.y = fmaf(z1.w, w.y, A1.y); A1.z = fmaf(z1.w, w.z, A1.z); A1.w = fmaf(z1.w, w.w, A1.w);
            A2.x = fmaf(z2.w, w.x, A2.x); A2.y = fmaf(z2.w, w.y, A2.y); A2.z = fmaf(z2.w, w.z, A2.z); A2.w = fmaf(z2.w, w.w, A2.w);
            A3.x = fmaf(z3.w, w.x, A3.x); A3.y = fmaf(z3.w, w.y, A3.y); A3.z = fmaf(z3.w, w.z, A3.z); A3.w = fmaf(z3.w, w.w, A3.w);
        }
        float4 bb = __ldg((const float4*)(bo + n4));
        float4 ov;
        ov.x = A0.x + bb.x; ov.y = A0.y + bb.y; ov.z = A0.z + bb.z; ov.w = A0.w + bb.w;
        *(float4*)(outp + OFF_OUT + (size_t)(b0 + sg4 + 0) * 1024 + n4) = ov;
        ov.x = A1.x + bb.x; ov.y = A1.y + bb.y; ov.z = A1.z + bb.z; ov.w = A1.w + bb.w;
        *(float4*)(outp + OFF_OUT + (size_t)(b0 + sg4 + 1) * 1024 + n4) = ov;
        ov.x = A2.x + bb.x; ov.y = A2.y + bb.y; ov.z = A2.z + bb.z; ov.w = A2.w + bb.w;
        *(float4*)(outp + OFF_OUT + (size_t)(b0 + sg4 + 2) * 1024 + n4) = ov;
        ov.x = A3.x + bb.x; ov.y = A3.y + bb.y; ov.z = A3.z + bb.z; ov.w = A3.w + bb.w;
        *(float4*)(outp + OFF_OUT + (size_t)(b0 + sg4 + 3) * 1024 + n4) = ov;
    }
}

// ---------------------------------------------------------------------------
extern "C" void kernel_launch(void* const* d_in, const int* in_sizes, int n_in,
                              void* d_out, int out_size)
{
    const float* x    = (const float*)d_in[0];
    const float* Wk   = (const float*)d_in[1];
    const float* bk   = (const float*)d_in[2];
    const float* Wv   = (const float*)d_in[3];
    const float* bv   = (const float*)d_in[4];
    const float* Wq   = (const float*)d_in[5];
    const float* bq   = (const float*)d_in[6];
    const float* Wo   = (const float*)d_in[7];
    const float* bo   = (const float*)d_in[8];
    const float* ln_g = (const float*)d_in[9];
    const float* ln_b = (const float*)d_in[10];
    const float* lr_w = (const float*)d_in[11];
    const float* lr_b = (const float*)d_in[12];
    const float* W1   = (const float*)d_in[13];
    const float* W2   = (const float*)d_in[14];
    float* outp = (float*)d_out;

    cudaFuncSetAttribute(mega_kernel,
                         cudaFuncAttributeMaxDynamicSharedMemorySize, MEGA_BYTES);

    proj_eta_kernel<<<448, 128>>>(x, Wk, bk, Wv, bv, Wq, bq, lr_w, lr_b);
    mega_kernel<<<128, 1024, MEGA_BYTES>>>(W1, W2, Wo, bo, ln_g, ln_b, outp);
}

// round 13
// speedup vs baseline: 1.6682x; 1.0405x over previous
#include <cuda_runtime.h>
#include <math.h>

#define BB 2048
#define DD 1024
#define RR 64
#define HH 256

// output layout: [out (B*1024)] [W1n (B*64*256)] [W2n (B*256*64)] [ssl_loss (B)]
#define OFF_OUT  0ull
#define OFF_W1   (2048ull*1024ull)
#define OFF_W2   (OFF_W1 + 2048ull*16384ull)
#define OFF_LOSS (OFF_W2 + 2048ull*16384ull)

__device__ float g_K [BB*RR];
__device__ float g_V [BB*RR];
__device__ float g_Q [BB*RR];
__device__ float g_K2[BB*RR];
__device__ float g_V2[BB*RR];
__device__ float g_Q2[BB*RR];
__device__ float g_eta[BB];

static __device__ __forceinline__ float wredsum(float v) {
#pragma unroll
    for (int o = 16; o; o >>= 1) v += __shfl_xor_sync(0xffffffffu, v, o);
    return v;
}

// fast tanh: 1 - 2/(e^{2x}+1)
static __device__ __forceinline__ float tanh_fast(float x) {
    float e = __expf(2.0f * x);
    return 1.0f - __fdividef(2.0f, e + 1.0f);
}

static __device__ __forceinline__ void gelu_fd(float x, float* y, float* dy) {
    const float c = 0.7978845608028654f;
    const float a = 0.044715f;
    float x2 = x * x;
    float u = c * (x + a * x * x2);
    float t = tanh_fast(u);
    float half1pt = 0.5f * (1.f + t);
    *y  = x * half1pt;
    *dy = half1pt + 0.5f * x * (1.f - t * t) * c * (1.f + 3.f * a * x2);
}

// ---------------------------------------------------------------------------
// proj + eta: 256 x 128-thread blocks.
//   bid < 192: proj; mat = bid/64, rem = bid%64, ksp = rem&1, m0 = (rem>>1)*64
//              64M x 64N tile, K half of 512, micro 8x4
//   bid >= 192: eta (32 rows each, 64 blocks, 4 warps x 8 rows)
// ---------------------------------------------------------------------------
__global__ void __launch_bounds__(128) proj_eta_kernel(
    const float* __restrict__ x,
    const float* __restrict__ Wk, const float* __restrict__ bk,
    const float* __restrict__ Wv, const float* __restrict__ bv,
    const float* __restrict__ Wq, const float* __restrict__ bq,
    const float* __restrict__ lr_w, const float* __restrict__ lr_b)
{
    const int tid = threadIdx.x;
    const int lane = tid & 31;
    const int wrp = tid >> 5;
    const int bid = blockIdx.x;

    if (bid >= 192) {
        int rbase = (bid - 192) * 32 + wrp * 8;
#pragma unroll
        for (int jj = 0; jj < 8; jj++) {
            int row = rbase + jj;
            const float* xr = x + (size_t)row * DD;
            float s = 0.f;
#pragma unroll 8
            for (int j = lane; j < DD; j += 32) s = fmaf(xr[j], lr_w[j], s);
            s = wredsum(s);
            if (lane == 0) g_eta[row] = 0.1f / (1.f + expf(-(s + lr_b[0])));
        }
        return;
    }

    const int mat = bid / 64;
    const int rem = bid % 64;
    const int ksp = rem & 1;
    const int m0  = (rem >> 1) * 64;
    const int k0  = ksp * 512;

    const float* W    = (mat == 0) ? Wk : (mat == 1) ? Wv : Wq;
    const float* bias = (mat == 0) ? bk : (mat == 1) ? bv : bq;
    float* Cout = (ksp == 0) ? ((mat == 0) ? g_K : (mat == 1) ? g_V : g_Q)
                             : ((mat == 0) ? g_K2 : (mat == 1) ? g_V2 : g_Q2);

    __shared__ float As[32][68];   // [k][m] 64 rows, padded
    __shared__ float Bs[32][64];   // [k][n]

    const int tx = tid & 15;       // n = tx*4
    const int ty = tid >> 4;       // m = ty*8

    float acc[8][4] = {};

    for (int kt = k0; kt < k0 + 512; kt += 32) {
        // A tile: 64 rows x 32 k -> 512 float4, 4 per thread, transposed
#pragma unroll
        for (int l = 0; l < 4; l++) {
            int li  = tid + l * 128;
            int row = li >> 3;
            int c4  = li & 7;
            float4 a = *(const float4*)(x + (size_t)(m0 + row) * DD + kt + c4 * 4);
            As[c4 * 4 + 0][row] = a.x;
            As[c4 * 4 + 1][row] = a.y;
            As[c4 * 4 + 2][row] = a.z;
            As[c4 * 4 + 3][row] = a.w;
        }
        // B tile: 32 k x 64 n -> 512 float4, 4 per thread
#pragma unroll
        for (int l = 0; l < 4; l++) {
            int li  = tid + l * 128;
            int row = li >> 4;
            int c4  = li & 15;
            *(float4*)(&Bs[row][c4 * 4]) =
                *(const float4*)(W + (size_t)(kt + row) * RR + c4 * 4);
        }
        __syncthreads();
#pragma unroll
        for (int k = 0; k < 32; k++) {
            float4 a0 = *(const float4*)(&As[k][ty * 8]);
            float4 a1 = *(const float4*)(&As[k][ty * 8 + 4]);
            float4 b  = *(const float4*)(&Bs[k][tx * 4]);
            acc[0][0] = fmaf(a0.x, b.x, acc[0][0]); acc[0][1] = fmaf(a0.x, b.y, acc[0][1]);
            acc[0][2] = fmaf(a0.x, b.z, acc[0][2]); acc[0][3] = fmaf(a0.x, b.w, acc[0][3]);
            acc[1][0] = fmaf(a0.y, b.x, acc[1][0]); acc[1][1] = fmaf(a0.y, b.y, acc[1][1]);
            acc[1][2] = fmaf(a0.y, b.z, acc[1][2]); acc[1][3] = fmaf(a0.y, b.w, acc[1][3]);
            acc[2][0] = fmaf(a0.z, b.x, acc[2][0]); acc[2][1] = fmaf(a0.z, b.y, acc[2][1]);
            acc[2][2] = fmaf(a0.z, b.z, acc[2][2]); acc[2][3] = fmaf(a0.z, b.w, acc[2][3]);
            acc[3][0] = fmaf(a0.w, b.x, acc[3][0]); acc[3][1] = fmaf(a0.w, b.y, acc[3][1]);
            acc[3][2] = fmaf(a0.w, b.z, acc[3][2]); acc[3][3] = fmaf(a0.w, b.w, acc[3][3]);
            acc[4][0] = fmaf(a1.x, b.x, acc[4][0]); acc[4][1] = fmaf(a1.x, b.y, acc[4][1]);
            acc[4][2] = fmaf(a1.x, b.z, acc[4][2]); acc[4][3] = fmaf(a1.x, b.w, acc[4][3]);
            acc[5][0] = fmaf(a1.y, b.x, acc[5][0]); acc[5][1] = fmaf(a1.y, b.y, acc[5][1]);
            acc[5][2] = fmaf(a1.y, b.z, acc[5][2]); acc[5][3] = fmaf(a1.y, b.w, acc[5][3]);
            acc[6][0] = fmaf(a1.z, b.x, acc[6][0]); acc[6][1] = fmaf(a1.z, b.y, acc[6][1]);
            acc[6][2] = fmaf(a1.z, b.z, acc[6][2]); acc[6][3] = fmaf(a1.z, b.w, acc[6][3]);
            acc[7][0] = fmaf(a1.w, b.x, acc[7][0]); acc[7][1] = fmaf(a1.w, b.y, acc[7][1]);
            acc[7][2] = fmaf(a1.w, b.z, acc[7][2]); acc[7][3] = fmaf(a1.w, b.w, acc[7][3]);
        }
        __syncthreads();
    }
#pragma unroll
    for (int i = 0; i < 8; i++) {
        int row = m0 + ty * 8 + i;
        int col = tx * 4;
        float4 o;
        if (ksp == 0) {
            o.x = acc[i][0] + bias[col];
            o.y = acc[i][1] + bias[col + 1];
            o.z = acc[i][2] + bias[col + 2];
            o.w = acc[i][3] + bias[col + 3];
        } else {
            o.x = acc[i][0]; o.y = acc[i][1]; o.z = acc[i][2]; o.w = acc[i][3];
        }
        *(float4*)(Cout + (size_t)row * RR + col) = o;
    }
}

// ---------------------------------------------------------------------------
// MEGA kernel: 128 blocks x 1024 threads, 16 samples/block.
// Store warps (16-31) cache their W-chunk in REGISTERS and loop over samples:
// zero LDG on the store path; all reads from smem.
// ---------------------------------------------------------------------------
#define CS 16
#define O_W1S   0
#define O_W2S   16384
#define O_KX    33792
#define O_VX    34816
#define O_QX    35840
#define O_EK    36864
#define O_LNG   37888
#define O_LNB   37952
#define O_HPRE  38016
#define O_HV    42112
#define O_GDY   46208
#define O_DHP   50304
#define O_ORR   54400
#define O_DOR   55424
#define O_ZL    56448
#define O_RED   57472
#define O_SCE   57600
#define O_SCQ   57616
#define O_SCH   57632
#define MEGA_FLOATS 57648
#define MEGA_BYTES  (MEGA_FLOATS * 4)

#define BAR_COMPUTE() asm volatile("bar.sync 1, 512;" ::: "memory")

__global__ void __launch_bounds__(1024, 1) mega_kernel(
    const float* __restrict__ W1, const float* __restrict__ W2,
    const float* __restrict__ Wo, const float* __restrict__ bo,
    const float* __restrict__ ln_g, const float* __restrict__ ln_b,
    float* __restrict__ outp)
{
    extern __shared__ float sm[];
    float* W1s  = sm + O_W1S;    // [64][256]
    float* W2s  = sm + O_W2S;    // [256][68]
    float* KX   = sm + O_KX;
    float* VX   = sm + O_VX;
    float* QX   = sm + O_QX;
    float* EK   = sm + O_EK;
    float* LNG  = sm + O_LNG;
    float* LNB  = sm + O_LNB;
    float* HPRE = sm + O_HPRE;   // [16][256] (becomes H2)
    float* HV   = sm + O_HV;     // [16][256] (P5 partial scratch later)
    float* GDY  = sm + O_GDY;    // [16][256]
    float* DHP  = sm + O_DHP;    // [16][256] (P2 partial scratch earlier)
    float* ORR  = sm + O_ORR;
    float* DOR  = sm + O_DOR;
    float* ZL   = sm + O_ZL;
    float* RED  = sm + O_RED;    // [16][8]
    float* SC_ETA = sm + O_SCE;
    float* SC_QK  = sm + O_SCQ;
    float* SC_HH  = sm + O_SCH;

    const int tid  = threadIdx.x;
    const int b0   = blockIdx.x * CS;
    const int lane = tid & 31;
    const int wrp  = tid >> 5;

    // ================= P0: stage =================
#pragma unroll
    for (int l = 0; l < 4; l++) {
        int i = (tid + l * 1024) * 4;
        *(float4*)(W1s + i) = __ldg((const float4*)(W1 + i));
    }
#pragma unroll
    for (int l = 0; l < 4; l++) {
        int i4 = tid + l * 1024;
        int idx = i4 * 4;
        int ii = idx >> 6, rr2 = idx & 63;
        float4 w = __ldg((const float4*)(W2 + idx));
        *(float4*)(W2s + ii * 68 + rr2) = w;
    }
    if (tid < 768) {
        int seg = tid >> 8, off = tid & 255;
        const float4* p0; const float4* p1; float* dst;
        if (seg == 0)      { p0 = (const float4*)(g_K + (size_t)b0 * 64); p1 = (const float4*)(g_K2 + (size_t)b0 * 64); dst = KX; }
        else if (seg == 1) { p0 = (const float4*)(g_V + (size_t)b0 * 64); p1 = (const float4*)(g_V2 + (size_t)b0 * 64); dst = VX; }
        else               { p0 = (const float4*)(g_Q + (size_t)b0 * 64); p1 = (const float4*)(g_Q2 + (size_t)b0 * 64); dst = QX; }
        float4 a = p0[off], b = p1[off];
        float4 o; o.x = a.x + b.x; o.y = a.y + b.y; o.z = a.z + b.z; o.w = a.w + b.w;
        *(float4*)(dst + off * 4) = o;
    }
    if (tid < 64) { LNG[tid] = ln_g[tid]; LNB[tid] = ln_b[tid]; }
    if (tid >= 64 && tid < 64 + CS) SC_ETA[tid - 64] = g_eta[b0 + tid - 64];
    __syncthreads();

    EK[tid] = SC_ETA[tid >> 6] * KX[tid];

    // ================= P1: hpre = k@W1, hv/gdy = gelu (all warps) =========
    {
        const int c  = tid & 255;
        const int sg = (tid >> 8) * 4;
        float a0 = 0.f, a1 = 0.f, a2 = 0.f, a3 = 0.f;
#pragma unroll
        for (int r4 = 0; r4 < 64; r4 += 4) {
            float w0 = W1s[(r4 + 0) * 256 + c];
            float w1 = W1s[(r4 + 1) * 256 + c];
            float w2 = W1s[(r4 + 2) * 256 + c];
            float w3 = W1s[(r4 + 3) * 256 + c];
            float4 k0 = *(const float4*)(KX + (sg + 0) * 64 + r4);
            float4 k1 = *(const float4*)(KX + (sg + 1) * 64 + r4);
            float4 k2 = *(const float4*)(KX + (sg + 2) * 64 + r4);
            float4 k3 = *(const float4*)(KX + (sg + 3) * 64 + r4);
            a0 = fmaf(w0, k0.x, fmaf(w1, k0.y, fmaf(w2, k0.z, fmaf(w3, k0.w, a0))));
            a1 = fmaf(w0, k1.x, fmaf(w1, k1.y, fmaf(w2, k1.z, fmaf(w3, k1.w, a1))));
            a2 = fmaf(w0, k2.x, fmaf(w1, k2.y, fmaf(w2, k2.z, fmaf(w3, k2.w, a2))));
            a3 = fmaf(w0, k3.x, fmaf(w1, k3.y, fmaf(w2, k3.z, fmaf(w3, k3.w, a3))));
        }
        float acc[4] = {a0, a1, a2, a3};
#pragma unroll
        for (int j = 0; j < 4; j++) {
            int s = sg + j;
            float y, dy;
            gelu_fd(acc[j], &y, &dy);
            HPRE[s * 256 + c] = acc[j];
            HV[s * 256 + c]   = y;
            GDY[s * 256 + c]  = dy;
        }
    }
    __syncthreads();

    // ================= P2: o = h@W2 (all warps, i-split x4) ===============
    {
        const int r  = tid & 63;
        const int ic = (tid >> 6) & 3;
        const int sg = (tid >> 8) * 4;
        const int ib = ic * 64;
        float a0 = 0.f, a1 = 0.f, a2 = 0.f, a3 = 0.f;
#pragma unroll
        for (int ii = 0; ii < 64; ii += 4) {
            int i = ib + ii;
            float w0 = W2s[(i + 0) * 68 + r];
            float w1 = W2s[(i + 1) * 68 + r];
            float w2 = W2s[(i + 2) * 68 + r];
            float w3 = W2s[(i + 3) * 68 + r];
            float4 h0 = *(const float4*)(HV + (sg + 0) * 256 + i);
            float4 h1 = *(const float4*)(HV + (sg + 1) * 256 + i);
            float4 h2 = *(const float4*)(HV + (sg + 2) * 256 + i);
            float4 h3 = *(const float4*)(HV + (sg + 3) * 256 + i);
            a0 = fmaf(w0, h0.x, fmaf(w1, h0.y, fmaf(w2, h0.z, fmaf(w3, h0.w, a0))));
            a1 = fmaf(w0, h1.x, fmaf(w1, h1.y, fmaf(w2, h1.z, fmaf(w3, h1.w, a1))));
            a2 = fmaf(w0, h2.x, fmaf(w1, h2.y, fmaf(w2, h2.z, fmaf(w3, h2.w, a2))));
            a3 = fmaf(w0, h3.x, fmaf(w1, h3.y, fmaf(w2, h3.z, fmaf(w3, h3.w, a3))));
        }
        DHP[ic * 1024 + (sg + 0) * 64 + r] = a0;
        DHP[ic * 1024 + (sg + 1) * 64 + r] = a1;
        DHP[ic * 1024 + (sg + 2) * 64 + r] = a2;
        DHP[ic * 1024 + (sg + 3) * 64 + r] = a3;
    }
    __syncthreads();
    {
        int s = tid >> 6, rr = tid & 63;
        int o = s * 64 + rr;
        ORR[o] = DHP[o] + DHP[1024 + o] + DHP[2048 + o] + DHP[3072 + o];
    }
    __syncthreads();

    // ================= P3: LN fwd + loss + LN bwd + qk (warps 0-15) =======
    if (wrp < CS) {
        int s = wrp;
        float o0 = ORR[s * 64 + lane], o1 = ORR[s * 64 + lane + 32];
        float mu = wredsum(o0 + o1) * (1.f / 64.f);
        float d0 = o0 - mu, d1 = o1 - mu;
        float var = wredsum(d0 * d0 + d1 * d1) * (1.f / 64.f);
        float sf = rsqrtf(var + 1e-6f);
        float n0 = d0 * sf, n1 = d1 * sf;
        float g0 = LNG[lane], g1 = LNG[lane + 32];
        float k0 = KX[s * 64 + lane], k1 = KX[s * 64 + lane + 32];
        float pred0 = k0 + n0 * g0 + LNB[lane];
        float pred1 = k1 + n1 * g1 + LNB[lane + 32];
        float e0 = pred0 - VX[s * 64 + lane], e1 = pred1 - VX[s * 64 + lane + 32];
        float loss = wredsum(e0 * e0 + e1 * e1) * (1.f / 64.f);
        float dn0 = e0 * (2.f / 64.f) * g0;
        float dn1 = e1 * (2.f / 64.f) * g1;
        float m1 = wredsum(dn0 + dn1) * (1.f / 64.f);
        float m2 = wredsum(dn0 * n0 + dn1 * n1) * (1.f / 64.f);
        DOR[s * 64 + lane]      = sf * (dn0 - m1 - n0 * m2);
        DOR[s * 64 + lane + 32] = sf * (dn1 - m1 - n1 * m2);
        float qk = wredsum(QX[s * 64 + lane] * k0 + QX[s * 64 + lane + 32] * k1);
        if (lane == 0) {
            SC_QK[s] = qk;
            outp[OFF_LOSS + b0 + s] = loss;
        }
    }
    __syncthreads();

    // ============ REGION 1: store warps W2n (reg-cached) || compute P4 =====
    if (wrp >= CS) {
        // warp sw holds W2 rows [16sw,16sw+16); loops all samples.
        const int sw = wrp - CS;
        const int r4 = lane & 15;
        const int ih = lane >> 4;
        float4 wreg[8];
#pragma unroll
        for (int j = 0; j < 8; j++) {
            int i = 16 * sw + 2 * j + ih;
            wreg[j] = *(const float4*)(W2s + i * 68 + r4 * 4);
        }
#pragma unroll 1
        for (int s = 0; s < CS; s++) {
            const float eta_s = SC_ETA[s];
            const float4 d = *(const float4*)(DOR + s * 64 + r4 * 4);
            const float* hvrow = HV + s * 256;
            float* dst = outp + OFF_W2 + (size_t)(b0 + s) * 16384;
#pragma unroll
            for (int j = 0; j < 8; j++) {
                int i = 16 * sw + 2 * j + ih;
                float sc = eta_s * hvrow[i];
                float4 ov;
                ov.x = wreg[j].x - sc * d.x;
                ov.y = wreg[j].y - sc * d.y;
                ov.z = wreg[j].z - sc * d.z;
                ov.w = wreg[j].w - sc * d.w;
                *(float4*)(dst + (i * 16 + r4) * 4) = ov;
            }
        }
    } else {
        const int c = tid & 255;
        const int sgh = (tid >> 8) * 8;
        float acc[8];
#pragma unroll
        for (int j = 0; j < 8; j++) acc[j] = 0.f;
#pragma unroll
        for (int r4 = 0; r4 < 64; r4 += 4) {
            float4 w4 = *(const float4*)(W2s + c * 68 + r4);
#pragma unroll
            for (int j = 0; j < 8; j++) {
                float4 d4 = *(const float4*)(DOR + (sgh + j) * 64 + r4);
                acc[j] = fmaf(w4.x, d4.x, fmaf(w4.y, d4.y,
                         fmaf(w4.z, d4.z, fmaf(w4.w, d4.w, acc[j]))));
            }
        }
#pragma unroll
        for (int j = 0; j < 8; j++) {
            int s = sgh + j;
            acc[j] *= GDY[s * 256 + c];
            DHP[s * 256 + c] = acc[j];
        }
#pragma unroll
        for (int j = 0; j < 8; j++) acc[j] = 0.f;
#pragma unroll
        for (int r4 = 0; r4 < 64; r4 += 4) {
            float w0 = W1s[(r4 + 0) * 256 + c];
            float w1 = W1s[(r4 + 1) * 256 + c];
            float w2 = W1s[(r4 + 2) * 256 + c];
            float w3 = W1s[(r4 + 3) * 256 + c];
#pragma unroll
            for (int j = 0; j < 8; j++) {
                float4 q4 = *(const float4*)(QX + (sgh + j) * 64 + r4);
                acc[j] = fmaf(w0, q4.x, fmaf(w1, q4.y,
                         fmaf(w2, q4.z, fmaf(w3, q4.w, acc[j]))));
            }
        }
#pragma unroll
        for (int j = 0; j < 8; j++) {
            int s = sgh + j;
            float eqk = SC_ETA[s] * SC_QK[s];
            float y, dyt;
            gelu_fd(acc[j] - eqk * DHP[s * 256 + c], &y, &dyt);
            HPRE[s * 256 + c] = y;
            float p = wredsum(y * HV[s * 256 + c]);
            if (lane == 0) RED[s * 8 + (wrp & 7)] = p;
        }
    }
    __syncthreads();   // A

    // ============ REGION 2: store warps W1n (reg-cached) || compute P5-P6 ==
    if (wrp >= CS) {
        // warp sw holds W1 rows [4sw,4sw+4) (8 float4 chunks per lane)
        const int sw = wrp - CS;
        float4 wreg[8];
#pragma unroll
        for (int j = 0; j < 8; j++) {
            int r = 4 * sw + (j >> 1);
            int c = (j & 1) * 32 + lane;
            wreg[j] = *(const float4*)(W1s + r * 256 + c * 4);
        }
#pragma unroll 1
        for (int s = 0; s < CS; s++) {
            const float4 d0 = *(const float4*)(DHP + s * 256 + lane * 4);
            const float4 d1 = *(const float4*)(DHP + s * 256 + (lane + 32) * 4);
            const float* ekrow = EK + s * 64;
            float* dst = outp + OFF_W1 + (size_t)(b0 + s) * 16384;
#pragma unroll
            for (int j = 0; j < 8; j++) {
                int r = 4 * sw + (j >> 1);
                int c = (j & 1) * 32 + lane;
                float sc = ekrow[r];
                float4 d = (j & 1) ? d1 : d0;
                float4 ov;
                ov.x = wreg[j].x - sc * d.x;
                ov.y = wreg[j].y - sc * d.y;
                ov.z = wreg[j].z - sc * d.z;
                ov.w = wreg[j].w - sc * d.w;
                *(float4*)(dst + (r * 64 + c) * 4) = ov;
            }
        }
        // no further named barriers; falls through to __syncthreads B
    } else {
        if (tid < CS) {
            float hh = 0.f;
#pragma unroll
            for (int w = 0; w < 8; w++) hh += RED[tid * 8 + w];
            SC_HH[tid] = hh;
        }
        // P5 partials: o2 = h2@W2, i-split x4, 8 samples per thread
        {
            const int r  = tid & 63;
            const int ic = (tid >> 6) & 3;
            const int sgh = (tid >> 8) * 8;
            const int ib = ic * 64;
            float acc[8];
#pragma unroll
            for (int j = 0; j < 8; j++) acc[j] = 0.f;
#pragma unroll
            for (int ii = 0; ii < 64; ii += 4) {
                int i = ib + ii;
                float w0 = W2s[(i + 0) * 68 + r];
                float w1 = W2s[(i + 1) * 68 + r];
                float w2 = W2s[(i + 2) * 68 + r];
                float w3 = W2s[(i + 3) * 68 + r];
#pragma unroll
                for (int j = 0; j < 8; j++) {
                    float4 h4 = *(const float4*)(HPRE + (sgh + j) * 256 + i);
                    acc[j] = fmaf(w0, h4.x, fmaf(w1, h4.y,
                             fmaf(w2, h4.z, fmaf(w3, h4.w, acc[j]))));
                }
            }
#pragma unroll
            for (int j = 0; j < 8; j++)
                HV[ic * 1024 + (sgh + j) * 64 + r] = acc[j];
        }
        BAR_COMPUTE();
        {
            int s = tid >> 6;
            int rr = tid & 63;
#pragma unroll
            for (int hh2 = 0; hh2 < 2; hh2++) {
                int sr = s + hh2 * 8;
                int o = sr * 64 + rr;
                float v = HV[o] + HV[1024 + o] + HV[2048 + o] + HV[3072 + o];
                ORR[o] = v - SC_ETA[sr] * SC_HH[sr] * DOR[o];
            }
        }
        BAR_COMPUTE();
        {
            int s = wrp;
            float o0 = ORR[s * 64 + lane], o1 = ORR[s * 64 + lane + 32];
            float mu = wredsum(o0 + o1) * (1.f / 64.f);
            float d0 = o0 - mu, d1 = o1 - mu;
            float var = wredsum(d0 * d0 + d1 * d1) * (1.f / 64.f);
            float sf = rsqrtf(var + 1e-6f);
            ZL[s * 64 + lane]      = QX[s * 64 + lane]      + (d0 * sf) * LNG[lane]      + LNB[lane];
            ZL[s * 64 + lane + 32] = QX[s * 64 + lane + 32] + (d1 * sf) * LNG[lane + 32] + LNB[lane + 32];
        }
    }
    __syncthreads();   // B

    // ================= P7: out = z @ Wo + bo (ALL 32 warps) ===============
    {
        const int sg4 = (tid >> 8) * 4;
        const int n4  = (tid & 255) * 4;
        float4 A0 = {0.f, 0.f, 0.f, 0.f}, A1 = A0, A2 = A0, A3 = A0;
#pragma unroll
        for (int r4 = 0; r4 < 64; r4 += 4) {
            float4 z0 = *(const float4*)(ZL + (sg4 + 0) * 64 + r4);
            float4 z1 = *(const float4*)(ZL + (sg4 + 1) * 64 + r4);
            float4 z2 = *(const float4*)(ZL + (sg4 + 2) * 64 + r4);
            float4 z3 = *(const float4*)(ZL + (sg4 + 3) * 64 + r4);
            float4 w;
            w = __ldg((const float4*)(Wo + (size_t)(r4 + 0) * 1024 + n4));
            A0.x = fmaf(z0.x, w.x, A0.x); A0.y = fmaf(z0.x, w.y, A0.y); A0.z = fmaf(z0.x, w.z, A0.z); A0.w = fmaf(z0.x, w.w, A0.w);
            A1.x = fmaf(z1.x, w.x, A1.x); A1.y = fmaf(z1.x, w.y, A1.y); A1.z = fmaf(z1.x, w.z, A1.z); A1.w = fmaf(z1.x, w.w, A1.w);
            A2.x = fmaf(z2.x, w.x, A2.x); A2.y = fmaf(z2.x, w.y, A2.y); A2.z = fmaf(z2.x, w.z, A2.z); A2.w = fmaf(z2.x, w.w, A2.w);
            A3.x = fmaf(z3.x, w.x, A3.x); A3.y = fmaf(z3.x, w.y, A3.y); A3.z = fmaf(z3.x, w.z, A3.z); A3.w = fmaf(z3.x, w.w, A3.w);
            w = __ldg((const float4*)(Wo + (size_t)(r4 + 1) * 1024 + n4));
            A0.x = fmaf(z0.y, w.x, A0.x); A0.y = fmaf(z0.y, w.y, A0.y); A0.z = fmaf(z0.y, w.z, A0.z); A0.w = fmaf(z0.y, w.w, A0.w);
            A1.x = fmaf(z1.y, w.x, A1.x); A1.y = fmaf(z1.y, w.y, A1.y); A1.z = fmaf(z1.y, w.z, A1.z); A1.w = fmaf(z1.y, w.w, A1.w);
            A2.x = fmaf(z2.y, w.x, A2.x); A2.y = fmaf(z2.y, w.y, A2.y); A2.z = fmaf(z2.y, w.z, A2.z); A2.w = fmaf(z2.y, w.w, A2.w);
            A3.x = fmaf(z3.y, w.x, A3.x); A3.y = fmaf(z3.y, w.y, A3.y); A3.z = fmaf(z3.y, w.z, A3.z); A3.w = fmaf(z3.y, w.w, A3.w);
            w = __ldg((const float4*)(Wo + (size_t)(r4 + 2) * 1024 + n4));
            A0.x = fmaf(z0.z, w.x, A0.x); A0.y = fmaf(z0.z, w.y, A0.y); A0.z = fmaf(z0.z, w.z, A0.z); A0.w = fmaf(z0.z, w.w, A0.w);
            A1.x = fmaf(z1.z, w.x, A1.x); A1.y = fmaf(z1.z, w.y, A1.y); A1.z = fmaf(z1.z, w.z, A1.z); A1.w = fmaf(z1.z, w.w, A1.w);
            A2.x = fmaf(z2.z, w.x, A2.x); A2.y = fmaf(z2.z, w.y, A2.y); A2.z = fmaf(z2.z, w.z, A2.z); A2.w = fmaf(z2.z, w.w, A2.w);
            A3.x = fmaf(z3.z, w.x, A3.x); A3.y = fmaf(z3.z, w.y, A3.y); A3.z = fmaf(z3.z, w.z, A3.z); A3.w = fmaf(z3.z, w.w, A3.w);
            w = __ldg((const float4*)(Wo + (size_t)(r4 + 3) * 1024 + n4));
            A0.x = fmaf(z0.w, w.x, A0.x); A0.y = fmaf(z0.w, w.y, A0.y); A0.z = fmaf(z0.w, w.z, A0.z); A0.w = fmaf(z0.w, w.w, A0.w);
            A1.x = fmaf(z1.w, w.x, A1.x); A1.y = fmaf(z1.w, w.y, A1.y); A1.z = fmaf(z1.w, w.z, A1.z); A1.w = fmaf(z1.w, w.w, A1.w);
            A2.x = fmaf(z2.w, w.x, A2.x); A2.y = fmaf(z2.w, w.y, A2.y); A2.z = fmaf(z2.w, w.z, A2.z); A2.w = fmaf(z2.w, w.w, A2.w);
            A3.x = fmaf(z3.w, w.x, A3.x); A3.y = fmaf(z3.w, w.y, A3.y); A3.z = fmaf(z3.w, w.z, A3.z); A3.w = fmaf(z3.w, w.w, A3.w);
        }
        float4 bb = __ldg((const float4*)(bo + n4));
        float4 ov;
        ov.x = A0.x + bb.x; ov.y = A0.y + bb.y; ov.z = A0.z + bb.z; ov.w = A0.w + bb.w;
        *(float4*)(outp + OFF_OUT + (size_t)(b0 + sg4 + 0) * 1024 + n4) = ov;
        ov.x = A1.x + bb.x; ov.y = A1.y + bb.y; ov.z = A1.z + bb.z; ov.w = A1.w + bb.w;
        *(float4*)(outp + OFF_OUT + (size_t)(b0 + sg4 + 1) * 1024 + n4) = ov;
        ov.x = A2.x + bb.x; ov.y = A2.y + bb.y; ov.z = A2.z + bb.z; ov.w = A2.w + bb.w;
        *(float4*)(outp + OFF_OUT + (size_t)(b0 + sg4 + 2) * 1024 + n4) = ov;
        ov.x = A3.x + bb.x; ov.y = A3.y + bb.y; ov.z = A3.z + bb.z; ov.w = A3.w + bb.w;
        *(float4*)(outp + OFF_OUT + (size_t)(b0 + sg4 + 3) * 1024 + n4) = ov;
    }
}

// ---------------------------------------------------------------------------
extern "C" void kernel_launch(void* const* d_in, const int* in_sizes, int n_in,
                              void* d_out, int out_size)
{
    const float* x    = (const float*)d_in[0];
    const float* Wk   = (const float*)d_in[1];
    const float* bk   = (const float*)d_in[2];
    const float* Wv   = (const float*)d_in[3];
    const float* bv   = (const float*)d_in[4];
    const float* Wq   = (const float*)d_in[5];
    const float* bq   = (const float*)d_in[6];
    const float* Wo   = (const float*)d_in[7];
    const float* bo   = (const float*)d_in[8];
    const float* ln_g = (const float*)d_in[9];
    const float* ln_b = (const float*)d_in[10];
    const float* lr_w = (const float*)d_in[11];
    const float* lr_b = (const float*)d_in[12];
    const float* W1   = (const float*)d_in[13];
    const float* W2   = (const float*)d_in[14];
    float* outp = (float*)d_out;

    cudaFuncSetAttribute(mega_kernel,
                         cudaFuncAttributeMaxDynamicSharedMemorySize, MEGA_BYTES);

    proj_eta_kernel<<<256, 128>>>(x, Wk, bk, Wv, bv, Wq, bq, lr_w, lr_b);
    mega_kernel<<<128, 1024, MEGA_BYTES>>>(W1, W2, Wo, bo, ln_g, ln_b, outp);
}